// round 1
// baseline (speedup 1.0000x reference)
#include <cuda_runtime.h>
#include <math.h>

#define LTOK 24576
#define SSP  1024
#define TT   24
#define CDIM 1536
#define HID  1024
#define NHEAD 16
#define DHEAD 64
#define NF   104
#define KHID 128

// ---------------- scratch (device globals; allocation-free rule) ----------------
__device__ float g_kc[NF * KHID];
__device__ float g_gm[TT * 24];
__device__ float g_kv[TT * 2048];
__device__ float g_h1[(size_t)LTOK * HID];
__device__ float g_h2[(size_t)LTOK * HID];
__device__ float g_qkv[(size_t)LTOK * 3 * HID];
__device__ float g_o[(size_t)LTOK * HID];
__device__ float g_hidden[(size_t)LTOK * CDIM];
__device__ float g_qh[(size_t)LTOK * HID];

// ---------------- generic 128x128x8 SGEMM with fused epilogues ----------------
// epi: 0 = bias(optional), 1 = bias+gelu(tanh), 2 = residual add (addsrc)
__global__ void __launch_bounds__(256) sgemm128(
    const float* __restrict__ A, int lda, int Ksplit, const float* __restrict__ A2,
    const float* __restrict__ B,
    float* __restrict__ Cout,
    const float* __restrict__ bias,
    const float* __restrict__ addsrc,
    int M, int N, int K, int epi)
{
    __shared__ float As[8][128];
    __shared__ float Bs[8][132];
    int tid = threadIdx.x;
    int rowBase = blockIdx.y * 128, colBase = blockIdx.x * 128;
    int aRow = tid >> 1, aCol = (tid & 1) << 2;
    int bRow = tid >> 5, bCol = (tid & 31) << 2;
    int ty = tid >> 4, tx = tid & 15;

    float acc[8][8];
#pragma unroll
    for (int i = 0; i < 8; i++)
#pragma unroll
        for (int j = 0; j < 8; j++) acc[i][j] = 0.f;

    const float* Aptr = A + (size_t)(rowBase + aRow) * lda;
    int gmrow = (rowBase + aRow) >> 10;  // token -> frame t (only used in GEMM1)

    for (int k0 = 0; k0 < K; k0 += 8) {
        int kk = k0 + aCol;
        float4 av;
        if (kk < Ksplit) av = *(const float4*)(Aptr + kk);
        else             av = *(const float4*)(A2 + gmrow * 24 + (kk - Ksplit));
        As[aCol + 0][aRow] = av.x; As[aCol + 1][aRow] = av.y;
        As[aCol + 2][aRow] = av.z; As[aCol + 3][aRow] = av.w;
        float4 bv = *(const float4*)(B + (size_t)(k0 + bRow) * N + colBase + bCol);
        *(float4*)&Bs[bRow][bCol] = bv;
        __syncthreads();
#pragma unroll
        for (int k = 0; k < 8; k++) {
            float ra[8], rb[8];
#pragma unroll
            for (int i = 0; i < 8; i++) ra[i] = As[k][ty * 8 + i];
#pragma unroll
            for (int j = 0; j < 8; j++) rb[j] = Bs[k][tx * 8 + j];
#pragma unroll
            for (int i = 0; i < 8; i++)
#pragma unroll
                for (int j = 0; j < 8; j++) acc[i][j] += ra[i] * rb[j];
        }
        __syncthreads();
    }

#pragma unroll
    for (int i = 0; i < 8; i++) {
        int row = rowBase + ty * 8 + i;
#pragma unroll
        for (int j = 0; j < 8; j++) {
            int col = colBase + tx * 8 + j;
            float v = acc[i][j];
            if (bias) v += bias[col];
            if (epi == 1) {
                float x3 = v * v * v;
                v = 0.5f * v * (1.f + tanhf(0.7978845608028654f * (v + 0.044715f * x3)));
            } else if (epi == 2) {
                v += addsrc[(size_t)row * N + col];
            }
            Cout[(size_t)row * N + col] = v;
        }
    }
}

// ---------------- LayerNorm over HID=1024, in place ----------------
__global__ void __launch_bounds__(256) ln_kernel(float* __restrict__ h,
                                                 const float* __restrict__ g,
                                                 const float* __restrict__ b)
{
    __shared__ float row[1024];
    __shared__ float red[8];
    __shared__ float meanv, rstdv;
    int r = blockIdx.x;
    float* hp = h + (size_t)r * 1024;
    int tid = threadIdx.x;
    float s = 0.f;
    for (int i = tid; i < 1024; i += 256) { float v = hp[i]; row[i] = v; s += v; }
    for (int o = 16; o; o >>= 1) s += __shfl_xor_sync(~0u, s, o);
    if ((tid & 31) == 0) red[tid >> 5] = s;
    __syncthreads();
    if (tid == 0) { float t = 0; for (int i = 0; i < 8; i++) t += red[i]; meanv = t * (1.f / 1024.f); }
    __syncthreads();
    float m = meanv;
    float ss = 0.f;
    for (int i = tid; i < 1024; i += 256) { float d = row[i] - m; ss += d * d; }
    for (int o = 16; o; o >>= 1) ss += __shfl_xor_sync(~0u, ss, o);
    if ((tid & 31) == 0) red[tid >> 5] = ss;
    __syncthreads();
    if (tid == 0) { float t = 0; for (int i = 0; i < 8; i++) t += red[i]; rstdv = rsqrtf(t * (1.f / 1024.f) + 1e-5f); }
    __syncthreads();
    float rs = rstdv;
    for (int i = tid; i < 1024; i += 256) hp[i] = (row[i] - m) * rs * g[i] + b[i];
}

// ---------------- RMSNorm + RoPE helpers ----------------
__device__ __forceinline__ float rope_apply(float nv, int d, int t) {
    float other = __shfl_xor_sync(~0u, nv, 1);
    if (d < 8) {
        float inv = exp2f(-2.f * (float)(d >> 1));   // {1, 1/4, 1/16, 1/64}
        float ang = (float)t * inv;
        float c, s;
        sincosf(ang, &s, &c);
        float rot = (d & 1) ? other : -other;
        nv = nv * c + rot * s;
    }
    return nv;
}

// q+k of qkv tensor, in place. grid(NHEAD, LTOK), block 128
__global__ void rmsrope_qk(float* __restrict__ qkv,
                           const float* __restrict__ qn, const float* __restrict__ kn)
{
    int h = blockIdx.x, r = blockIdx.y;
    int which = threadIdx.x >> 6, d = threadIdx.x & 63;
    int t = r >> 10;
    float* base = qkv + (size_t)r * 3072 + which * 1024 + h * 64;
    float v = base[d];
    float ss = v * v;
    for (int o = 16; o; o >>= 1) ss += __shfl_xor_sync(~0u, ss, o);
    __shared__ float wsum[4];
    int warp = threadIdx.x >> 5;
    if ((threadIdx.x & 31) == 0) wsum[warp] = ss;
    __syncthreads();
    float tot = wsum[which * 2] + wsum[which * 2 + 1];
    const float* w = which ? kn : qn;
    float nv = v * rsqrtf(tot * (1.f / 64.f) + 1e-6f) * w[d];
    base[d] = rope_apply(nv, d, t);
}

// single head-major array, in place. grid(NHEAD, rows), block 64. t = r >> tshift
__global__ void rmsrope_vec(float* __restrict__ ptr, const float* __restrict__ w,
                            int rowstride, int tshift)
{
    int h = blockIdx.x, r = blockIdx.y;
    int d = threadIdx.x;
    int t = r >> tshift;
    float* base = ptr + (size_t)r * rowstride + h * 64;
    float v = base[d];
    float ss = v * v;
    for (int o = 16; o; o >>= 1) ss += __shfl_xor_sync(~0u, ss, o);
    __shared__ float wsum[2];
    if ((d & 31) == 0) wsum[d >> 5] = ss;
    __syncthreads();
    float tot = wsum[0] + wsum[1];
    float nv = v * rsqrtf(tot * (1.f / 64.f) + 1e-6f) * w[d];
    base[d] = rope_apply(nv, d, t);
}

// ---------------- local causal attention (window 6, DH=64): one warp per query ----------------
__global__ void __launch_bounds__(256) attn1(const float* __restrict__ qkv, float* __restrict__ o)
{
    int item = blockIdx.x * 8 + (threadIdx.x >> 5);
    int lane = threadIdx.x & 31;
    int t = item % 24;
    int sh = item / 24;
    int h = sh & 15;
    int s = sh >> 4;
    int u0 = max(0, t - 5);
    int nu = t - u0 + 1;

    const float* qp = qkv + (size_t)(t * 1024 + s) * 3072 + h * 64;
    float q0 = qp[lane], q1 = qp[lane + 32];
    float sc[6];
    float mx = -1e30f;
#pragma unroll
    for (int i = 0; i < 6; i++) {
        if (i < nu) {
            int u = u0 + i;
            const float* kp = qkv + (size_t)(u * 1024 + s) * 3072 + 1024 + h * 64;
            float d = q0 * kp[lane] + q1 * kp[lane + 32];
            for (int off = 16; off; off >>= 1) d += __shfl_xor_sync(~0u, d, off);
            sc[i] = d * 0.125f;
            mx = fmaxf(mx, sc[i]);
        }
    }
    float denom = 0.f, a0 = 0.f, a1 = 0.f;
#pragma unroll
    for (int i = 0; i < 6; i++) {
        if (i < nu) {
            float p = __expf(sc[i] - mx);
            denom += p;
            int u = u0 + i;
            const float* vp = qkv + (size_t)(u * 1024 + s) * 3072 + 2048 + h * 64;
            a0 += p * vp[lane]; a1 += p * vp[lane + 32];
        }
    }
    float inv = 1.f / denom;
    float* op = o + (size_t)(t * 1024 + s) * 1024 + h * 64;
    op[lane] = a0 * inv; op[lane + 32] = a1 * inv;
}

// keyboard cross-attention: keys/values shared per frame. one warp per (token, head)
__global__ void __launch_bounds__(256) attn2(const float* __restrict__ q,
                                             const float* __restrict__ kv,
                                             float* __restrict__ o)
{
    int item = blockIdx.x * 8 + (threadIdx.x >> 5);
    int lane = threadIdx.x & 31;
    int h = item & 15;
    int r = item >> 4;
    int t = r >> 10;
    int u0 = max(0, t - 5);
    int nu = t - u0 + 1;

    const float* qp = q + (size_t)r * 1024 + h * 64;
    float q0 = qp[lane], q1 = qp[lane + 32];
    float sc[6];
    float mx = -1e30f;
#pragma unroll
    for (int i = 0; i < 6; i++) {
        if (i < nu) {
            int u = u0 + i;
            const float* kp = kv + (size_t)u * 2048 + h * 64;
            float d = q0 * kp[lane] + q1 * kp[lane + 32];
            for (int off = 16; off; off >>= 1) d += __shfl_xor_sync(~0u, d, off);
            sc[i] = d * 0.125f;
            mx = fmaxf(mx, sc[i]);
        }
    }
    float denom = 0.f, a0 = 0.f, a1 = 0.f;
#pragma unroll
    for (int i = 0; i < 6; i++) {
        if (i < nu) {
            float p = __expf(sc[i] - mx);
            denom += p;
            int u = u0 + i;
            const float* vp = kv + (size_t)u * 2048 + 1024 + h * 64;
            a0 += p * vp[lane]; a1 += p * vp[lane + 32];
        }
    }
    float inv = 1.f / denom;
    float* op = o + (size_t)r * 1024 + h * 64;
    op[lane] = a0 * inv; op[lane + 32] = a1 * inv;
}

// ---------------- tiny conditioning path ----------------
// kc = silu(keyboard @ kb_w1 + b1) @ kb_w2 + b2 ; also gather mouse -> g_gm
__global__ void kb_mlp(const float* __restrict__ kb,
                       const float* __restrict__ w1, const float* __restrict__ b1,
                       const float* __restrict__ w2, const float* __restrict__ b2,
                       const float* __restrict__ mouse)
{
    int c = threadIdx.x;  // 128 threads
    for (int i = c; i < TT * 24; i += 128) {
        int t = i / 24, j2 = i % 24;
        g_gm[i] = mouse[(4 * t + (j2 >> 1)) * 2 + (j2 & 1)];
    }
    __shared__ float hid[128];
    for (int n = 0; n < NF; n++) {
        float a = b1[c];
#pragma unroll
        for (int i = 0; i < 6; i++) a += kb[n * 6 + i] * w1[i * 128 + c];
        hid[c] = a / (1.f + __expf(-a));   // silu
        __syncthreads();
        float ov = b2[c];
        for (int i = 0; i < 128; i++) ov += hid[i] * w2[i * 128 + c];
        g_kc[n * 128 + c] = ov;
        __syncthreads();
    }
}

// kv[t] = gk[t] @ wkv_key   (gk[t] = kc[4t..4t+11] flattened, 1536 -> 2048)
__global__ void kv_gemm(const float* __restrict__ wkv)
{
    int t = blockIdx.x;
    __shared__ float gk[1536];
    for (int i = threadIdx.x; i < 1536; i += 256)
        gk[i] = g_kc[(4 * t + i / 128) * 128 + (i & 127)];
    __syncthreads();
    for (int oc = threadIdx.x; oc < 2048; oc += 256) {
        float a = 0.f;
        for (int i = 0; i < 1536; i++) a += gk[i] * wkv[(size_t)i * 2048 + oc];
        g_kv[t * 2048 + oc] = a;
    }
}

// ---------------- host ----------------
extern "C" void kernel_launch(void* const* d_in, const int* in_sizes, int n_in,
                              void* d_out, int out_size)
{
    // Input index layout: dict order puts scalars tt,th,tw at 3..5; be robust to
    // the alternative (weights at 3, scalars at the end).
    int wb = (in_sizes[3] == 1) ? 6 : 3;
    const float* x       = (const float*)d_in[0];
    const float* mouse   = (const float*)d_in[1];
    const float* kb      = (const float*)d_in[2];
    const float* kb_w1   = (const float*)d_in[wb + 0];
    const float* kb_b1   = (const float*)d_in[wb + 1];
    const float* kb_w2   = (const float*)d_in[wb + 2];
    const float* kb_b2   = (const float*)d_in[wb + 3];
    const float* mm_w1   = (const float*)d_in[wb + 4];
    const float* mm_b1   = (const float*)d_in[wb + 5];
    const float* mm_w2   = (const float*)d_in[wb + 6];
    const float* mm_b2   = (const float*)d_in[wb + 7];
    const float* ln_g    = (const float*)d_in[wb + 8];
    const float* ln_b    = (const float*)d_in[wb + 9];
    const float* qkv_w   = (const float*)d_in[wb + 10];
    const float* qn_img  = (const float*)d_in[wb + 11];
    const float* kn_img  = (const float*)d_in[wb + 12];
    const float* qn_key  = (const float*)d_in[wb + 13];
    const float* kn_key  = (const float*)d_in[wb + 14];
    const float* proj_mouse_w = (const float*)d_in[wb + 15];
    const float* wq_key  = (const float*)d_in[wb + 16];
    const float* wkv_key = (const float*)d_in[wb + 17];
    const float* proj_key_w   = (const float*)d_in[wb + 18];

    float *p_gm, *p_kv, *p_h1, *p_h2, *p_qkv, *p_o, *p_hidden, *p_qh;
    cudaGetSymbolAddress((void**)&p_gm, g_gm);
    cudaGetSymbolAddress((void**)&p_kv, g_kv);
    cudaGetSymbolAddress((void**)&p_h1, g_h1);
    cudaGetSymbolAddress((void**)&p_h2, g_h2);
    cudaGetSymbolAddress((void**)&p_qkv, g_qkv);
    cudaGetSymbolAddress((void**)&p_o, g_o);
    cudaGetSymbolAddress((void**)&p_hidden, g_hidden);
    cudaGetSymbolAddress((void**)&p_qh, g_qh);

    // conditioning path (tiny)
    kb_mlp<<<1, 128>>>(kb, kb_w1, kb_b1, kb_w2, kb_b2, mouse);
    kv_gemm<<<TT, 256>>>(wkv_key);
    rmsrope_vec<<<dim3(NHEAD, TT), 64>>>(p_kv, kn_key, 2048, 0);

    const int MB = LTOK / 128;  // 192

    // GEMM1: [x | gm] @ mm_w1 + b1, gelu  (K=1560, split at 1536)
    sgemm128<<<dim3(HID / 128, MB), 256>>>(x, CDIM, CDIM, p_gm, mm_w1, p_h1,
                                           mm_b1, nullptr, LTOK, HID, 1560, 1);
    // GEMM2: h1 @ mm_w2 + b2
    sgemm128<<<dim3(HID / 128, MB), 256>>>(p_h1, HID, HID, nullptr, mm_w2, p_h2,
                                           mm_b2, nullptr, LTOK, HID, HID, 0);
    ln_kernel<<<LTOK, 256>>>(p_h2, ln_g, ln_b);

    // GEMM3: qkv
    sgemm128<<<dim3(3 * HID / 128, MB), 256>>>(p_h2, HID, HID, nullptr, qkv_w, p_qkv,
                                               nullptr, nullptr, LTOK, 3 * HID, HID, 0);
    rmsrope_qk<<<dim3(NHEAD, LTOK), 128>>>(p_qkv, qn_img, kn_img);
    attn1<<<(SSP * NHEAD * TT) / 8, 256>>>(p_qkv, p_o);

    // GEMM4: hidden = x + o @ proj_mouse_w
    sgemm128<<<dim3(CDIM / 128, MB), 256>>>(p_o, HID, HID, nullptr, proj_mouse_w, p_hidden,
                                            nullptr, x, LTOK, CDIM, HID, 2);
    // GEMM5: qh = hidden @ wq_key
    sgemm128<<<dim3(HID / 128, MB), 256>>>(p_hidden, CDIM, CDIM, nullptr, wq_key, p_qh,
                                           nullptr, nullptr, LTOK, HID, CDIM, 0);
    rmsrope_vec<<<dim3(NHEAD, LTOK), 64>>>(p_qh, qn_key, HID, 10);
    attn2<<<(LTOK * NHEAD) / 8, 256>>>(p_qh, p_kv, p_o);

    // GEMM6: out = hidden + o2 @ proj_key_w
    sgemm128<<<dim3(CDIM / 128, MB), 256>>>(p_o, HID, HID, nullptr, proj_key_w, (float*)d_out,
                                            nullptr, p_hidden, LTOK, CDIM, HID, 2);
}

// round 2
// speedup vs baseline: 2.1333x; 2.1333x over previous
#include <cuda_runtime.h>
#include <math.h>
#include <stdint.h>

#define LTOK 24576
#define SSP  1024
#define TT   24
#define CDIM 1536
#define HID  1024
#define NHEAD 16
#define DHEAD 64
#define NF   104
#define KHID 128

// ---------------- scratch (device globals; allocation-free rule) ----------------
__device__ float g_kc[NF * KHID];
__device__ float g_gm[TT * 24];
__device__ float g_kv[TT * 2048];
__device__ float g_h1[(size_t)LTOK * HID];
__device__ float g_h2[(size_t)LTOK * HID];
__device__ float g_qkv[(size_t)LTOK * 3 * HID];
__device__ float g_o[(size_t)LTOK * HID];
__device__ float g_hidden[(size_t)LTOK * CDIM];
__device__ float g_qh[(size_t)LTOK * HID];

// ---------------- TF32 tensor-core GEMM, 128x128 tile, fused epilogues ----------------
// epi: 0 = bias(optional), 1 = bias+gelu(tanh), 2 = residual add (addsrc)
#define APITCH 36
#define BPITCH 132
#define ABUF (128 * APITCH)
#define BBUF (32 * BPITCH)
#define SMEM_WORDS (2 * ABUF + 2 * BBUF)

__device__ __forceinline__ uint32_t f2tf32(float x) {
    uint32_t r;
    asm("cvt.rna.tf32.f32 %0, %1;" : "=r"(r) : "f"(x));
    return r;
}

__device__ __forceinline__ void mma8(float* c, const uint32_t* a, const uint32_t* b) {
    asm volatile(
        "mma.sync.aligned.m16n8k8.row.col.f32.tf32.tf32.f32 "
        "{%0,%1,%2,%3}, {%4,%5,%6,%7}, {%8,%9}, {%0,%1,%2,%3};"
        : "+f"(c[0]), "+f"(c[1]), "+f"(c[2]), "+f"(c[3])
        : "r"(a[0]), "r"(a[1]), "r"(a[2]), "r"(a[3]), "r"(b[0]), "r"(b[1]));
}

__global__ void __launch_bounds__(256) tgemm(
    const float* __restrict__ A, int lda, int Ksplit, const float* __restrict__ A2,
    const float* __restrict__ B,
    float* __restrict__ Cout,
    const float* __restrict__ bias,
    const float* __restrict__ addsrc,
    int M, int N, int K, int epi)
{
    extern __shared__ uint32_t smem[];
    uint32_t* AsmBase = smem;
    uint32_t* BsmBase = smem + 2 * ABUF;

    int tid = threadIdx.x;
    int rowBase = blockIdx.y * 128, colBase = blockIdx.x * 128;
    int lane = tid & 31, warp = tid >> 5;
    int wm = warp & 1, wn = warp >> 1;          // 2 x 4 warps -> 64x32 warp tile

    // A loader: 2 threads per row, 16 consecutive floats each
    int aRow = tid >> 1, aCol = (tid & 1) << 4;
    // B loader: 8 threads per row, 16 consecutive floats each
    int bRow = tid >> 3, bCol = (tid & 7) << 4;

    const float* Aptr = A + (size_t)(rowBase + aRow) * lda;
    int gmrow = (rowBase + aRow) >> 10;

    float regA[16], regB[16];
    float acc[4][4][4];
#pragma unroll
    for (int mt = 0; mt < 4; mt++)
#pragma unroll
        for (int nt = 0; nt < 4; nt++)
#pragma unroll
            for (int r = 0; r < 4; r++) acc[mt][nt][r] = 0.f;

    int nk = (K + 31) / 32;

#define LOAD_A(K0)                                                         \
    {                                                                      \
        _Pragma("unroll")                                                  \
        for (int i = 0; i < 16; i += 4) {                                  \
            int kk = (K0) + aCol + i;                                      \
            float4 v;                                                      \
            if (kk + 3 < Ksplit) {                                         \
                v = *(const float4*)(Aptr + kk);                           \
            } else {                                                       \
                _Pragma("unroll")                                          \
                for (int j = 0; j < 4; j++) {                              \
                    int kj = kk + j;                                       \
                    float t;                                               \
                    if (kj < Ksplit)      t = Aptr[kj];                    \
                    else if (kj < K)      t = A2[gmrow * 24 + (kj - Ksplit)]; \
                    else                  t = 0.f;                         \
                    ((float*)&v)[j] = t;                                   \
                }                                                          \
            }                                                              \
            regA[i] = v.x; regA[i + 1] = v.y; regA[i + 2] = v.z; regA[i + 3] = v.w; \
        }                                                                  \
    }

#define LOAD_B(K0)                                                         \
    {                                                                      \
        int kk = (K0) + bRow;                                              \
        if (kk < K) {                                                      \
            const float* bp = B + (size_t)kk * N + colBase + bCol;         \
            _Pragma("unroll")                                              \
            for (int i = 0; i < 16; i += 4) {                              \
                float4 v = *(const float4*)(bp + i);                       \
                regB[i] = v.x; regB[i + 1] = v.y; regB[i + 2] = v.z; regB[i + 3] = v.w; \
            }                                                              \
        } else {                                                           \
            _Pragma("unroll")                                              \
            for (int i = 0; i < 16; i++) regB[i] = 0.f;                    \
        }                                                                  \
    }

#define STS_AB(BUF)                                                        \
    {                                                                      \
        uint32_t* pa = AsmBase + (BUF) * ABUF + aRow * APITCH + aCol;      \
        _Pragma("unroll")                                                  \
        for (int i = 0; i < 16; i += 4) {                                  \
            uint4 u;                                                       \
            u.x = f2tf32(regA[i]);     u.y = f2tf32(regA[i + 1]);          \
            u.z = f2tf32(regA[i + 2]); u.w = f2tf32(regA[i + 3]);          \
            *(uint4*)(pa + i) = u;                                         \
        }                                                                  \
        uint32_t* pb = BsmBase + (BUF) * BBUF + bRow * BPITCH + bCol;      \
        _Pragma("unroll")                                                  \
        for (int i = 0; i < 16; i += 4) {                                  \
            uint4 u;                                                       \
            u.x = f2tf32(regB[i]);     u.y = f2tf32(regB[i + 1]);          \
            u.z = f2tf32(regB[i + 2]); u.w = f2tf32(regB[i + 3]);          \
            *(uint4*)(pb + i) = u;                                         \
        }                                                                  \
    }

#define COMPUTE(BUF)                                                       \
    {                                                                      \
        const uint32_t* Ab = AsmBase + (BUF) * ABUF;                       \
        const uint32_t* Bb = BsmBase + (BUF) * BBUF;                       \
        _Pragma("unroll")                                                  \
        for (int kk = 0; kk < 4; kk++) {                                   \
            uint32_t afr[4][4], bfr[4][2];                                 \
            int krow = kk * 8 + (lane & 3);                                \
            int mrow = wm * 64 + (lane >> 2);                              \
            _Pragma("unroll")                                              \
            for (int mt = 0; mt < 4; mt++) {                               \
                const uint32_t* ap = Ab + (mrow + mt * 16) * APITCH + krow;\
                afr[mt][0] = ap[0];                                        \
                afr[mt][1] = ap[8 * APITCH];                               \
                afr[mt][2] = ap[4];                                        \
                afr[mt][3] = ap[8 * APITCH + 4];                           \
            }                                                              \
            int ncol = wn * 32 + (lane >> 2);                              \
            _Pragma("unroll")                                              \
            for (int nt = 0; nt < 4; nt++) {                               \
                const uint32_t* bp = Bb + krow * BPITCH + ncol + nt * 8;   \
                bfr[nt][0] = bp[0];                                        \
                bfr[nt][1] = bp[4 * BPITCH];                               \
            }                                                              \
            _Pragma("unroll")                                              \
            for (int mt = 0; mt < 4; mt++)                                 \
                _Pragma("unroll")                                          \
                for (int nt = 0; nt < 4; nt++)                             \
                    mma8(acc[mt][nt], afr[mt], bfr[nt]);                   \
        }                                                                  \
    }

    LOAD_A(0);
    LOAD_B(0);
    STS_AB(0);
    __syncthreads();
    int cur = 0;
    for (int t = 1; t < nk; t++) {
        LOAD_A(t * 32);
        LOAD_B(t * 32);
        COMPUTE(cur);
        STS_AB(cur ^ 1);
        __syncthreads();
        cur ^= 1;
    }
    COMPUTE(cur);

    // epilogue: write float2 pairs (c0,c1) and (c2,c3)
#pragma unroll
    for (int mt = 0; mt < 4; mt++) {
#pragma unroll
        for (int nt = 0; nt < 4; nt++) {
            int col = colBase + wn * 32 + nt * 8 + (lane & 3) * 2;
#pragma unroll
            for (int half = 0; half < 2; half++) {
                int row = rowBase + wm * 64 + mt * 16 + (lane >> 2) + half * 8;
                float v0 = acc[mt][nt][half * 2 + 0];
                float v1 = acc[mt][nt][half * 2 + 1];
                if (bias) { v0 += bias[col]; v1 += bias[col + 1]; }
                if (epi == 1) {
                    float x3 = v0 * v0 * v0;
                    v0 = 0.5f * v0 * (1.f + tanhf(0.7978845608028654f * (v0 + 0.044715f * x3)));
                    x3 = v1 * v1 * v1;
                    v1 = 0.5f * v1 * (1.f + tanhf(0.7978845608028654f * (v1 + 0.044715f * x3)));
                } else if (epi == 2) {
                    float2 a = *(const float2*)(addsrc + (size_t)row * N + col);
                    v0 += a.x; v1 += a.y;
                }
                float2 o; o.x = v0; o.y = v1;
                *(float2*)(Cout + (size_t)row * N + col) = o;
            }
        }
    }
}

// ---------------- LayerNorm over HID=1024, in place ----------------
__global__ void __launch_bounds__(256) ln_kernel(float* __restrict__ h,
                                                 const float* __restrict__ g,
                                                 const float* __restrict__ b)
{
    __shared__ float row[1024];
    __shared__ float red[8];
    __shared__ float meanv, rstdv;
    int r = blockIdx.x;
    float* hp = h + (size_t)r * 1024;
    int tid = threadIdx.x;
    float s = 0.f;
    for (int i = tid; i < 1024; i += 256) { float v = hp[i]; row[i] = v; s += v; }
    for (int o = 16; o; o >>= 1) s += __shfl_xor_sync(~0u, s, o);
    if ((tid & 31) == 0) red[tid >> 5] = s;
    __syncthreads();
    if (tid == 0) { float t = 0; for (int i = 0; i < 8; i++) t += red[i]; meanv = t * (1.f / 1024.f); }
    __syncthreads();
    float m = meanv;
    float ss = 0.f;
    for (int i = tid; i < 1024; i += 256) { float d = row[i] - m; ss += d * d; }
    for (int o = 16; o; o >>= 1) ss += __shfl_xor_sync(~0u, ss, o);
    if ((tid & 31) == 0) red[tid >> 5] = ss;
    __syncthreads();
    if (tid == 0) { float t = 0; for (int i = 0; i < 8; i++) t += red[i]; rstdv = rsqrtf(t * (1.f / 1024.f) + 1e-5f); }
    __syncthreads();
    float rs = rstdv;
    for (int i = tid; i < 1024; i += 256) hp[i] = (row[i] - m) * rs * g[i] + b[i];
}

// ---------------- RMSNorm + RoPE helpers ----------------
__device__ __forceinline__ float rope_apply(float nv, int d, int t) {
    float other = __shfl_xor_sync(~0u, nv, 1);
    if (d < 8) {
        float inv = exp2f(-2.f * (float)(d >> 1));
        float ang = (float)t * inv;
        float c, s;
        sincosf(ang, &s, &c);
        float rot = (d & 1) ? other : -other;
        nv = nv * c + rot * s;
    }
    return nv;
}

__global__ void rmsrope_qk(float* __restrict__ qkv,
                           const float* __restrict__ qn, const float* __restrict__ kn)
{
    int h = blockIdx.x, r = blockIdx.y;
    int which = threadIdx.x >> 6, d = threadIdx.x & 63;
    int t = r >> 10;
    float* base = qkv + (size_t)r * 3072 + which * 1024 + h * 64;
    float v = base[d];
    float ss = v * v;
    for (int o = 16; o; o >>= 1) ss += __shfl_xor_sync(~0u, ss, o);
    __shared__ float wsum[4];
    int warp = threadIdx.x >> 5;
    if ((threadIdx.x & 31) == 0) wsum[warp] = ss;
    __syncthreads();
    float tot = wsum[which * 2] + wsum[which * 2 + 1];
    const float* w = which ? kn : qn;
    float nv = v * rsqrtf(tot * (1.f / 64.f) + 1e-6f) * w[d];
    base[d] = rope_apply(nv, d, t);
}

__global__ void rmsrope_vec(float* __restrict__ ptr, const float* __restrict__ w,
                            int rowstride, int tshift)
{
    int h = blockIdx.x, r = blockIdx.y;
    int d = threadIdx.x;
    int t = r >> tshift;
    float* base = ptr + (size_t)r * rowstride + h * 64;
    float v = base[d];
    float ss = v * v;
    for (int o = 16; o; o >>= 1) ss += __shfl_xor_sync(~0u, ss, o);
    __shared__ float wsum[2];
    if ((d & 31) == 0) wsum[d >> 5] = ss;
    __syncthreads();
    float tot = wsum[0] + wsum[1];
    float nv = v * rsqrtf(tot * (1.f / 64.f) + 1e-6f) * w[d];
    base[d] = rope_apply(nv, d, t);
}

// ---------------- local causal attention (window 6, DH=64) ----------------
__global__ void __launch_bounds__(256) attn1(const float* __restrict__ qkv, float* __restrict__ o)
{
    int item = blockIdx.x * 8 + (threadIdx.x >> 5);
    int lane = threadIdx.x & 31;
    int t = item % 24;
    int sh = item / 24;
    int h = sh & 15;
    int s = sh >> 4;
    int u0 = max(0, t - 5);
    int nu = t - u0 + 1;

    const float* qp = qkv + (size_t)(t * 1024 + s) * 3072 + h * 64;
    float q0 = qp[lane], q1 = qp[lane + 32];
    float sc[6];
    float mx = -1e30f;
#pragma unroll
    for (int i = 0; i < 6; i++) {
        if (i < nu) {
            int u = u0 + i;
            const float* kp = qkv + (size_t)(u * 1024 + s) * 3072 + 1024 + h * 64;
            float d = q0 * kp[lane] + q1 * kp[lane + 32];
            for (int off = 16; off; off >>= 1) d += __shfl_xor_sync(~0u, d, off);
            sc[i] = d * 0.125f;
            mx = fmaxf(mx, sc[i]);
        }
    }
    float denom = 0.f, a0 = 0.f, a1 = 0.f;
#pragma unroll
    for (int i = 0; i < 6; i++) {
        if (i < nu) {
            float p = __expf(sc[i] - mx);
            denom += p;
            int u = u0 + i;
            const float* vp = qkv + (size_t)(u * 1024 + s) * 3072 + 2048 + h * 64;
            a0 += p * vp[lane]; a1 += p * vp[lane + 32];
        }
    }
    float inv = 1.f / denom;
    float* op = o + (size_t)(t * 1024 + s) * 1024 + h * 64;
    op[lane] = a0 * inv; op[lane + 32] = a1 * inv;
}

__global__ void __launch_bounds__(256) attn2(const float* __restrict__ q,
                                             const float* __restrict__ kv,
                                             float* __restrict__ o)
{
    int item = blockIdx.x * 8 + (threadIdx.x >> 5);
    int lane = threadIdx.x & 31;
    int h = item & 15;
    int r = item >> 4;
    int t = r >> 10;
    int u0 = max(0, t - 5);
    int nu = t - u0 + 1;

    const float* qp = q + (size_t)r * 1024 + h * 64;
    float q0 = qp[lane], q1 = qp[lane + 32];
    float sc[6];
    float mx = -1e30f;
#pragma unroll
    for (int i = 0; i < 6; i++) {
        if (i < nu) {
            int u = u0 + i;
            const float* kp = kv + (size_t)u * 2048 + h * 64;
            float d = q0 * kp[lane] + q1 * kp[lane + 32];
            for (int off = 16; off; off >>= 1) d += __shfl_xor_sync(~0u, d, off);
            sc[i] = d * 0.125f;
            mx = fmaxf(mx, sc[i]);
        }
    }
    float denom = 0.f, a0 = 0.f, a1 = 0.f;
#pragma unroll
    for (int i = 0; i < 6; i++) {
        if (i < nu) {
            float p = __expf(sc[i] - mx);
            denom += p;
            int u = u0 + i;
            const float* vp = kv + (size_t)u * 2048 + 1024 + h * 64;
            a0 += p * vp[lane]; a1 += p * vp[lane + 32];
        }
    }
    float inv = 1.f / denom;
    float* op = o + (size_t)r * 1024 + h * 64;
    op[lane] = a0 * inv; op[lane + 32] = a1 * inv;
}

// ---------------- tiny conditioning path ----------------
__global__ void kb_mlp(const float* __restrict__ kb,
                       const float* __restrict__ w1, const float* __restrict__ b1,
                       const float* __restrict__ w2, const float* __restrict__ b2,
                       const float* __restrict__ mouse)
{
    int c = threadIdx.x;
    for (int i = c; i < TT * 24; i += 128) {
        int t = i / 24, j2 = i % 24;
        g_gm[i] = mouse[(4 * t + (j2 >> 1)) * 2 + (j2 & 1)];
    }
    __shared__ float hid[128];
    for (int n = 0; n < NF; n++) {
        float a = b1[c];
#pragma unroll
        for (int i = 0; i < 6; i++) a += kb[n * 6 + i] * w1[i * 128 + c];
        hid[c] = a / (1.f + __expf(-a));
        __syncthreads();
        float ov = b2[c];
        for (int i = 0; i < 128; i++) ov += hid[i] * w2[i * 128 + c];
        g_kc[n * 128 + c] = ov;
        __syncthreads();
    }
}

__global__ void kv_gemm(const float* __restrict__ wkv)
{
    int t = blockIdx.x;
    __shared__ float gk[1536];
    for (int i = threadIdx.x; i < 1536; i += 256)
        gk[i] = g_kc[(4 * t + i / 128) * 128 + (i & 127)];
    __syncthreads();
    for (int oc = threadIdx.x; oc < 2048; oc += 256) {
        float a = 0.f;
        for (int i = 0; i < 1536; i++) a += gk[i] * wkv[(size_t)i * 2048 + oc];
        g_kv[t * 2048 + oc] = a;
    }
}

// ---------------- host ----------------
extern "C" void kernel_launch(void* const* d_in, const int* in_sizes, int n_in,
                              void* d_out, int out_size)
{
    int wb = (in_sizes[3] == 1) ? 6 : 3;
    const float* x       = (const float*)d_in[0];
    const float* mouse   = (const float*)d_in[1];
    const float* kb      = (const float*)d_in[2];
    const float* kb_w1   = (const float*)d_in[wb + 0];
    const float* kb_b1   = (const float*)d_in[wb + 1];
    const float* kb_w2   = (const float*)d_in[wb + 2];
    const float* kb_b2   = (const float*)d_in[wb + 3];
    const float* mm_w1   = (const float*)d_in[wb + 4];
    const float* mm_b1   = (const float*)d_in[wb + 5];
    const float* mm_w2   = (const float*)d_in[wb + 6];
    const float* mm_b2   = (const float*)d_in[wb + 7];
    const float* ln_g    = (const float*)d_in[wb + 8];
    const float* ln_b    = (const float*)d_in[wb + 9];
    const float* qkv_w   = (const float*)d_in[wb + 10];
    const float* qn_img  = (const float*)d_in[wb + 11];
    const float* kn_img  = (const float*)d_in[wb + 12];
    const float* qn_key  = (const float*)d_in[wb + 13];
    const float* kn_key  = (const float*)d_in[wb + 14];
    const float* proj_mouse_w = (const float*)d_in[wb + 15];
    const float* wq_key  = (const float*)d_in[wb + 16];
    const float* wkv_key = (const float*)d_in[wb + 17];
    const float* proj_key_w   = (const float*)d_in[wb + 18];

    float *p_gm, *p_kv, *p_h1, *p_h2, *p_qkv, *p_o, *p_hidden, *p_qh;
    cudaGetSymbolAddress((void**)&p_gm, g_gm);
    cudaGetSymbolAddress((void**)&p_kv, g_kv);
    cudaGetSymbolAddress((void**)&p_h1, g_h1);
    cudaGetSymbolAddress((void**)&p_h2, g_h2);
    cudaGetSymbolAddress((void**)&p_qkv, g_qkv);
    cudaGetSymbolAddress((void**)&p_o, g_o);
    cudaGetSymbolAddress((void**)&p_hidden, g_hidden);
    cudaGetSymbolAddress((void**)&p_qh, g_qh);

    const int SMEM_BYTES = SMEM_WORDS * 4;  // 70656
    cudaFuncSetAttribute(tgemm, cudaFuncAttributeMaxDynamicSharedMemorySize, SMEM_BYTES);

    // conditioning path (tiny)
    kb_mlp<<<1, 128>>>(kb, kb_w1, kb_b1, kb_w2, kb_b2, mouse);
    kv_gemm<<<TT, 256>>>(wkv_key);
    rmsrope_vec<<<dim3(NHEAD, TT), 64>>>(p_kv, kn_key, 2048, 0);

    const int MB = LTOK / 128;  // 192

    // GEMM1: [x | gm] @ mm_w1 + b1, gelu  (K=1560, split at 1536)
    tgemm<<<dim3(HID / 128, MB), 256, SMEM_BYTES>>>(x, CDIM, CDIM, p_gm, mm_w1, p_h1,
                                                    mm_b1, nullptr, LTOK, HID, 1560, 1);
    // GEMM2: h1 @ mm_w2 + b2
    tgemm<<<dim3(HID / 128, MB), 256, SMEM_BYTES>>>(p_h1, HID, HID, nullptr, mm_w2, p_h2,
                                                    mm_b2, nullptr, LTOK, HID, HID, 0);
    ln_kernel<<<LTOK, 256>>>(p_h2, ln_g, ln_b);

    // GEMM3: qkv
    tgemm<<<dim3(3 * HID / 128, MB), 256, SMEM_BYTES>>>(p_h2, HID, HID, nullptr, qkv_w, p_qkv,
                                                        nullptr, nullptr, LTOK, 3 * HID, HID, 0);
    rmsrope_qk<<<dim3(NHEAD, LTOK), 128>>>(p_qkv, qn_img, kn_img);
    attn1<<<(SSP * NHEAD * TT) / 8, 256>>>(p_qkv, p_o);

    // GEMM4: hidden = x + o @ proj_mouse_w
    tgemm<<<dim3(CDIM / 128, MB), 256, SMEM_BYTES>>>(p_o, HID, HID, nullptr, proj_mouse_w, p_hidden,
                                                     nullptr, x, LTOK, CDIM, HID, 2);
    // GEMM5: qh = hidden @ wq_key
    tgemm<<<dim3(HID / 128, MB), 256, SMEM_BYTES>>>(p_hidden, CDIM, CDIM, nullptr, wq_key, p_qh,
                                                    nullptr, nullptr, LTOK, HID, CDIM, 0);
    rmsrope_vec<<<dim3(NHEAD, LTOK), 64>>>(p_qh, qn_key, HID, 10);
    attn2<<<(LTOK * NHEAD) / 8, 256>>>(p_qh, p_kv, p_o);

    // GEMM6: out = hidden + o2 @ proj_key_w
    tgemm<<<dim3(CDIM / 128, MB), 256, SMEM_BYTES>>>(p_o, HID, HID, nullptr, proj_key_w, (float*)d_out,
                                                     nullptr, p_hidden, LTOK, CDIM, HID, 2);
}

// round 4
// speedup vs baseline: 3.1006x; 1.4534x over previous
#include <cuda_runtime.h>
#include <math.h>
#include <stdint.h>

#define LTOK 24576
#define SSP  1024
#define TT   24
#define CDIM 1536
#define HID  1024
#define NHEAD 16
#define NF   104

// ---------------- scratch (device globals; allocation-free rule) ----------------
__device__ __align__(128) float g_kc[NF * 128];
__device__ __align__(128) float g_gm[TT * 24];
__device__ __align__(128) float g_kv[TT * 2048];
__device__ __align__(128) float g_h1[(size_t)LTOK * HID];
__device__ __align__(128) float g_h2[(size_t)LTOK * HID];
__device__ __align__(128) float g_qkv[(size_t)LTOK * 3 * HID];
__device__ __align__(128) float g_o[(size_t)LTOK * HID];
__device__ __align__(128) float g_hidden[(size_t)LTOK * CDIM];
__device__ __align__(128) float g_qh[(size_t)LTOK * HID];
// transposed weights [N][K]
__device__ __align__(128) float g_wt1[1024 * 1560];
__device__ __align__(128) float g_wt2[1024 * 1024];
__device__ __align__(128) float g_wt3[3072 * 1024];
__device__ __align__(128) float g_wt4[1536 * 1024];
__device__ __align__(128) float g_wt5[1024 * 1536];
__device__ __align__(128) float g_wt6[1536 * 1024];

// ---------------- weight transpose ----------------
__global__ void transpose_k(const float* __restrict__ in, float* __restrict__ out,
                            int R, int C)
{
    __shared__ float t[32][33];
    int c0 = blockIdx.x * 32, r0 = blockIdx.y * 32;
    int x = threadIdx.x, y = threadIdx.y;  // 32 x 8
#pragma unroll
    for (int i = 0; i < 32; i += 8) {
        int r = r0 + y + i, c = c0 + x;
        t[y + i][x] = (r < R && c < C) ? in[(size_t)r * C + c] : 0.f;
    }
    __syncthreads();
#pragma unroll
    for (int i = 0; i < 32; i += 8) {
        int r = c0 + y + i, c = r0 + x;  // out is [C][R]
        if (r < C && c < R) out[(size_t)r * R + c] = t[x][y + i];
    }
}

// ---------------- TF32 tensor-core GEMM: cp.async 3-stage + ldmatrix ----------------
#define STAGES 3
#define STBYTES 32768            // per stage: A 16KB + B 16KB
#define GEMM_SMEM (STAGES * STBYTES)

__device__ __forceinline__ void mma8(float* c, uint32_t a0, uint32_t a1, uint32_t a2,
                                     uint32_t a3, uint32_t b0, uint32_t b1) {
    asm volatile(
        "mma.sync.aligned.m16n8k8.row.col.f32.tf32.tf32.f32 "
        "{%0,%1,%2,%3}, {%4,%5,%6,%7}, {%8,%9}, {%0,%1,%2,%3};"
        : "+f"(c[0]), "+f"(c[1]), "+f"(c[2]), "+f"(c[3])
        : "r"(a0), "r"(a1), "r"(a2), "r"(a3), "r"(b0), "r"(b1));
}

#define LDSM4(P, ADDR)                                                   \
    asm volatile("ldmatrix.sync.aligned.m8n8.x4.b16 {%0,%1,%2,%3}, [%4];" \
                 : "=r"((P)[0]), "=r"((P)[1]), "=r"((P)[2]), "=r"((P)[3]) \
                 : "r"(ADDR))

__device__ __forceinline__ void cpa16(uint32_t dst, const void* src, int sz) {
    asm volatile("cp.async.cg.shared.global [%0], [%1], 16, %2;\n"
                 :: "r"(dst), "l"(src), "r"(sz));
}

__global__ void __launch_bounds__(256, 2) tgemm(
    const float* __restrict__ A, int lda, int Ksplit, const float* __restrict__ A2,
    const float* __restrict__ Bt, int ldb,
    float* __restrict__ Cout,
    const float* __restrict__ bias,
    const float* __restrict__ addsrc,
    int M, int N, int K, int epi)
{
    extern __shared__ float smem[];
    const int tid = threadIdx.x, lane = tid & 31, warp = tid >> 5;
    const int wm = warp & 1, wn = warp >> 1;            // 2x4 warps -> 64x32 tiles
    const int rowBase = blockIdx.y * 128, colBase = blockIdx.x * 128;
    const int nk = (K + 31) >> 5;
    uint32_t sbase = (uint32_t)__cvta_generic_to_shared(smem);

    // loader constants: each thread owns unit u of rows row0+32i (i<4) for A and B
    const int row0 = tid >> 3;
    const int u = tid & 7;
    const uint32_t dstA0 = sbase + (uint32_t)(row0 * 128 + ((u ^ (row0 & 7)) << 4));
    const uint32_t dstB0 = dstA0 + 16384;

    // compute-side constants
    const int mtx = lane >> 3, rl = lane & 7;
    const int rA = wm * 64 + ((mtx >> 1) << 3) + rl;
    const int rB = wn * 32 + ((mtx >> 1) << 3) + rl;
    const int usel = mtx & 1;
    const int axor = rA & 7, bxor = rB & 7;
    const uint32_t aoff = (uint32_t)(rA * 128);
    const uint32_t boff = (uint32_t)(16384 + rB * 128);

    float acc[4][4][4];
#pragma unroll
    for (int a = 0; a < 4; a++)
#pragma unroll
        for (int b = 0; b < 4; b++)
#pragma unroll
            for (int c = 0; c < 4; c++) acc[a][b][c] = 0.f;

#define ISSUE(KT, STG)                                                        \
    {                                                                         \
        int kw = (KT) * 32 + u * 4;                                           \
        uint32_t sA = dstA0 + (STG) * STBYTES;                                \
        uint32_t sB = dstB0 + (STG) * STBYTES;                                \
        _Pragma("unroll")                                                     \
        for (int i = 0; i < 4; i++) {                                         \
            int r = row0 + 32 * i;                                            \
            const float* srcA; int pA = 16;                                   \
            if (kw + 4 <= Ksplit)                                             \
                srcA = A + (size_t)(rowBase + r) * lda + kw;                  \
            else if (kw + 4 <= K)                                             \
                srcA = A2 + ((rowBase + r) >> 10) * 24 + (kw - Ksplit);       \
            else { srcA = A; pA = 0; }                                        \
            cpa16(sA + i * 4096, srcA, pA);                                   \
            const float* srcB; int pB = 16;                                   \
            if (kw + 4 <= K)                                                  \
                srcB = Bt + (size_t)(colBase + r) * ldb + kw;                 \
            else { srcB = Bt; pB = 0; }                                       \
            cpa16(sB + i * 4096, srcB, pB);                                   \
        }                                                                     \
        asm volatile("cp.async.commit_group;\n");                             \
    }

#define COMPUTE(STG)                                                          \
    {                                                                         \
        uint32_t sb = sbase + (STG) * STBYTES;                                \
        _Pragma("unroll")                                                     \
        for (int kk = 0; kk < 4; kk++) {                                      \
            uint32_t ua = (uint32_t)(((2 * kk + usel) ^ axor) << 4);          \
            uint32_t ub = (uint32_t)(((2 * kk + usel) ^ bxor) << 4);          \
            uint32_t afr[4][4], bfr[2][4];                                    \
            _Pragma("unroll")                                                 \
            for (int mt = 0; mt < 4; mt++)                                    \
                LDSM4(afr[mt], sb + aoff + ua + mt * 2048);                   \
            _Pragma("unroll")                                                 \
            for (int p = 0; p < 2; p++)                                       \
                LDSM4(bfr[p], sb + boff + ub + p * 2048);                     \
            _Pragma("unroll")                                                 \
            for (int mt = 0; mt < 4; mt++) {                                  \
                mma8(acc[mt][0], afr[mt][0], afr[mt][2], afr[mt][1], afr[mt][3], bfr[0][0], bfr[0][1]); \
                mma8(acc[mt][1], afr[mt][0], afr[mt][2], afr[mt][1], afr[mt][3], bfr[0][2], bfr[0][3]); \
                mma8(acc[mt][2], afr[mt][0], afr[mt][2], afr[mt][1], afr[mt][3], bfr[1][0], bfr[1][1]); \
                mma8(acc[mt][3], afr[mt][0], afr[mt][2], afr[mt][1], afr[mt][3], bfr[1][2], bfr[1][3]); \
            }                                                                 \
        }                                                                     \
    }

    ISSUE(0, 0);
    ISSUE(1, 1);
    for (int t = 0; t < nk; t++) {
        asm volatile("cp.async.wait_group %0;\n" :: "n"(STAGES - 2));
        __syncthreads();
        int pf = t + STAGES - 1;
        if (pf < nk) { ISSUE(pf, pf % STAGES); }
        else { asm volatile("cp.async.commit_group;\n"); }
        COMPUTE(t % STAGES);
    }

    // epilogue
#pragma unroll
    for (int mt = 0; mt < 4; mt++) {
#pragma unroll
        for (int nt = 0; nt < 4; nt++) {
            int col = colBase + wn * 32 + nt * 8 + (lane & 3) * 2;
#pragma unroll
            for (int half = 0; half < 2; half++) {
                int row = rowBase + wm * 64 + mt * 16 + (lane >> 2) + half * 8;
                float v0 = acc[mt][nt][half * 2 + 0];
                float v1 = acc[mt][nt][half * 2 + 1];
                if (bias) { v0 += bias[col]; v1 += bias[col + 1]; }
                if (epi == 1) {
                    float x3 = v0 * v0 * v0;
                    v0 = 0.5f * v0 * (1.f + tanhf(0.7978845608028654f * (v0 + 0.044715f * x3)));
                    x3 = v1 * v1 * v1;
                    v1 = 0.5f * v1 * (1.f + tanhf(0.7978845608028654f * (v1 + 0.044715f * x3)));
                } else if (epi == 2) {
                    float2 a = *(const float2*)(addsrc + (size_t)row * N + col);
                    v0 += a.x; v1 += a.y;
                }
                float2 o; o.x = v0; o.y = v1;
                *(float2*)(Cout + (size_t)row * N + col) = o;
            }
        }
    }
#undef ISSUE
#undef COMPUTE
}

// ---------------- LayerNorm over HID=1024, in place ----------------
__global__ void __launch_bounds__(256) ln_kernel(float* __restrict__ h,
                                                 const float* __restrict__ g,
                                                 const float* __restrict__ b)
{
    __shared__ float row[1024];
    __shared__ float red[8];
    __shared__ float meanv, rstdv;
    int r = blockIdx.x;
    float* hp = h + (size_t)r * 1024;
    int tid = threadIdx.x;
    float s = 0.f;
    for (int i = tid; i < 1024; i += 256) { float v = hp[i]; row[i] = v; s += v; }
    for (int o = 16; o; o >>= 1) s += __shfl_xor_sync(~0u, s, o);
    if ((tid & 31) == 0) red[tid >> 5] = s;
    __syncthreads();
    if (tid == 0) { float t = 0; for (int i = 0; i < 8; i++) t += red[i]; meanv = t * (1.f / 1024.f); }
    __syncthreads();
    float m = meanv;
    float ss = 0.f;
    for (int i = tid; i < 1024; i += 256) { float d = row[i] - m; ss += d * d; }
    for (int o = 16; o; o >>= 1) ss += __shfl_xor_sync(~0u, ss, o);
    if ((tid & 31) == 0) red[tid >> 5] = ss;
    __syncthreads();
    if (tid == 0) { float t = 0; for (int i = 0; i < 8; i++) t += red[i]; rstdv = rsqrtf(t * (1.f / 1024.f) + 1e-5f); }
    __syncthreads();
    float rs = rstdv;
    for (int i = tid; i < 1024; i += 256) hp[i] = (row[i] - m) * rs * g[i] + b[i];
}

// ---------------- fused RMSNorm + RoPE (register-level, per warp row) ----------------
__device__ __forceinline__ void rmsrope_w(float& v0, float& v1,
                                          const float* __restrict__ w, int lane, int t)
{
    float ss = v0 * v0 + v1 * v1;
    for (int o = 16; o; o >>= 1) ss += __shfl_xor_sync(~0u, ss, o);
    float rs = rsqrtf(ss * (1.f / 64.f) + 1e-6f);
    v0 = v0 * rs * w[lane];
    v1 = v1 * rs * w[lane + 32];
    float other = __shfl_xor_sync(~0u, v0, 1);
    if (lane < 8) {
        float inv = exp2f(-2.f * (float)(lane >> 1));
        float ang = (float)t * inv;
        float c, s;
        sincosf(ang, &s, &c);
        float rot = (lane & 1) ? other : -other;
        v0 = v0 * c + rot * s;
    }
}

// standalone version for the small kv array (24 rows)
__global__ void rmsrope_vec(float* __restrict__ ptr, const float* __restrict__ w,
                            int rowstride, int tshift)
{
    int h = blockIdx.x, r = blockIdx.y;
    int lane = threadIdx.x & 31;
    int t = r >> tshift;
    float* base = ptr + (size_t)r * rowstride + h * 64;
    float v0 = base[lane], v1 = base[lane + 32];
    rmsrope_w(v0, v1, w, lane, t);
    base[lane] = v0; base[lane + 32] = v1;
}

// ---------------- attn1: local causal window-6, fused q/k rms+rope ----------------
__global__ void __launch_bounds__(256) attn1(const float* __restrict__ qkv,
                                             float* __restrict__ o,
                                             const float* __restrict__ qn,
                                             const float* __restrict__ kn)
{
    int item = blockIdx.x * 8 + (threadIdx.x >> 5);
    int lane = threadIdx.x & 31;
    int t = item % 24;
    int sh = item / 24;
    int h = sh & 15;
    int s = sh >> 4;
    int u0 = max(0, t - 5);
    int nu = t - u0 + 1;

    const float* qp = qkv + (size_t)(t * 1024 + s) * 3072 + h * 64;
    float q0 = qp[lane], q1 = qp[lane + 32];
    rmsrope_w(q0, q1, qn, lane, t);

    float sc[6];
    float mx = -1e30f;
#pragma unroll
    for (int i = 0; i < 6; i++) {
        if (i < nu) {
            int uu = u0 + i;
            const float* kp = qkv + (size_t)(uu * 1024 + s) * 3072 + 1024 + h * 64;
            float k0 = kp[lane], k1 = kp[lane + 32];
            rmsrope_w(k0, k1, kn, lane, uu);
            float d = q0 * k0 + q1 * k1;
            for (int off = 16; off; off >>= 1) d += __shfl_xor_sync(~0u, d, off);
            sc[i] = d * 0.125f;
            mx = fmaxf(mx, sc[i]);
        }
    }
    float denom = 0.f, a0 = 0.f, a1 = 0.f;
#pragma unroll
    for (int i = 0; i < 6; i++) {
        if (i < nu) {
            float p = __expf(sc[i] - mx);
            denom += p;
            int uu = u0 + i;
            const float* vp = qkv + (size_t)(uu * 1024 + s) * 3072 + 2048 + h * 64;
            a0 += p * vp[lane]; a1 += p * vp[lane + 32];
        }
    }
    float inv = 1.f / denom;
    float* op = o + (size_t)(t * 1024 + s) * 1024 + h * 64;
    op[lane] = a0 * inv; op[lane + 32] = a1 * inv;
}

// ---------------- attn2: keyboard cross-attn, fused q rms+rope ----------------
__global__ void __launch_bounds__(256) attn2(const float* __restrict__ q,
                                             const float* __restrict__ kv,
                                             float* __restrict__ o,
                                             const float* __restrict__ qn)
{
    int item = blockIdx.x * 8 + (threadIdx.x >> 5);
    int lane = threadIdx.x & 31;
    int h = item & 15;
    int r = item >> 4;
    int t = r >> 10;
    int u0 = max(0, t - 5);
    int nu = t - u0 + 1;

    const float* qp = q + (size_t)r * 1024 + h * 64;
    float q0 = qp[lane], q1 = qp[lane + 32];
    rmsrope_w(q0, q1, qn, lane, t);

    float sc[6];
    float mx = -1e30f;
#pragma unroll
    for (int i = 0; i < 6; i++) {
        if (i < nu) {
            int uu = u0 + i;
            const float* kp = kv + (size_t)uu * 2048 + h * 64;
            float d = q0 * kp[lane] + q1 * kp[lane + 32];
            for (int off = 16; off; off >>= 1) d += __shfl_xor_sync(~0u, d, off);
            sc[i] = d * 0.125f;
            mx = fmaxf(mx, sc[i]);
        }
    }
    float denom = 0.f, a0 = 0.f, a1 = 0.f;
#pragma unroll
    for (int i = 0; i < 6; i++) {
        if (i < nu) {
            float p = __expf(sc[i] - mx);
            denom += p;
            int uu = u0 + i;
            const float* vp = kv + (size_t)uu * 2048 + 1024 + h * 64;
            a0 += p * vp[lane]; a1 += p * vp[lane + 32];
        }
    }
    float inv = 1.f / denom;
    float* op = o + (size_t)r * 1024 + h * 64;
    op[lane] = a0 * inv; op[lane + 32] = a1 * inv;
}

// ---------------- tiny conditioning path ----------------
__global__ void gather_mouse(const float* __restrict__ mouse)
{
    int i = threadIdx.x;
    if (i < TT * 24) {
        int t = i / 24, j2 = i % 24;
        g_gm[i] = mouse[(4 * t + (j2 >> 1)) * 2 + (j2 & 1)];
    }
}

__global__ void kb_mlp(const float* __restrict__ kb,
                       const float* __restrict__ w1, const float* __restrict__ b1,
                       const float* __restrict__ w2, const float* __restrict__ b2)
{
    int n = blockIdx.x;
    int c = threadIdx.x;  // 128
    __shared__ float hid[128];
    float a = b1[c];
#pragma unroll
    for (int i = 0; i < 6; i++) a += kb[n * 6 + i] * w1[i * 128 + c];
    hid[c] = a / (1.f + __expf(-a));
    __syncthreads();
    float ov = b2[c];
    for (int i = 0; i < 128; i++) ov += hid[i] * w2[i * 128 + c];
    g_kc[n * 128 + c] = ov;
}

__global__ void kv_gemm(const float* __restrict__ wkv)
{
    int t = blockIdx.x;
    __shared__ float gk[1536];
    for (int i = threadIdx.x; i < 1536; i += 256)
        gk[i] = g_kc[(4 * t + i / 128) * 128 + (i & 127)];
    __syncthreads();
    for (int oc = threadIdx.x; oc < 2048; oc += 256) {
        float a = 0.f;
        for (int i = 0; i < 1536; i++) a += gk[i] * wkv[(size_t)i * 2048 + oc];
        g_kv[t * 2048 + oc] = a;
    }
}

// ---------------- host ----------------
extern "C" void kernel_launch(void* const* d_in, const int* in_sizes, int n_in,
                              void* d_out, int out_size)
{
    int wb = (in_sizes[3] == 1) ? 6 : 3;
    const float* x       = (const float*)d_in[0];
    const float* mouse   = (const float*)d_in[1];
    const float* kb      = (const float*)d_in[2];
    const float* kb_w1   = (const float*)d_in[wb + 0];
    const float* kb_b1   = (const float*)d_in[wb + 1];
    const float* kb_w2   = (const float*)d_in[wb + 2];
    const float* kb_b2   = (const float*)d_in[wb + 3];
    const float* mm_w1   = (const float*)d_in[wb + 4];
    const float* mm_b1   = (const float*)d_in[wb + 5];
    const float* mm_w2   = (const float*)d_in[wb + 6];
    const float* mm_b2   = (const float*)d_in[wb + 7];
    const float* ln_g    = (const float*)d_in[wb + 8];
    const float* ln_b    = (const float*)d_in[wb + 9];
    const float* qkv_w   = (const float*)d_in[wb + 10];
    const float* qn_img  = (const float*)d_in[wb + 11];
    const float* kn_img  = (const float*)d_in[wb + 12];
    const float* qn_key  = (const float*)d_in[wb + 13];
    const float* kn_key  = (const float*)d_in[wb + 14];
    const float* proj_mouse_w = (const float*)d_in[wb + 15];
    const float* wq_key  = (const float*)d_in[wb + 16];
    const float* wkv_key = (const float*)d_in[wb + 17];
    const float* proj_key_w   = (const float*)d_in[wb + 18];

    float *p_kv, *p_h1, *p_h2, *p_qkv, *p_o, *p_hidden, *p_qh, *p_gm;
    float *w1t, *w2t, *w3t, *w4t, *w5t, *w6t;
    cudaGetSymbolAddress((void**)&p_gm, g_gm);
    cudaGetSymbolAddress((void**)&p_kv, g_kv);
    cudaGetSymbolAddress((void**)&p_h1, g_h1);
    cudaGetSymbolAddress((void**)&p_h2, g_h2);
    cudaGetSymbolAddress((void**)&p_qkv, g_qkv);
    cudaGetSymbolAddress((void**)&p_o, g_o);
    cudaGetSymbolAddress((void**)&p_hidden, g_hidden);
    cudaGetSymbolAddress((void**)&p_qh, g_qh);
    cudaGetSymbolAddress((void**)&w1t, g_wt1);
    cudaGetSymbolAddress((void**)&w2t, g_wt2);
    cudaGetSymbolAddress((void**)&w3t, g_wt3);
    cudaGetSymbolAddress((void**)&w4t, g_wt4);
    cudaGetSymbolAddress((void**)&w5t, g_wt5);
    cudaGetSymbolAddress((void**)&w6t, g_wt6);

    cudaFuncSetAttribute(tgemm, cudaFuncAttributeMaxDynamicSharedMemorySize, GEMM_SMEM);

    dim3 tb(32, 8);
    transpose_k<<<dim3(32, 49), tb>>>(mm_w1, w1t, 1560, 1024);
    transpose_k<<<dim3(32, 32), tb>>>(mm_w2, w2t, 1024, 1024);
    transpose_k<<<dim3(96, 32), tb>>>(qkv_w, w3t, 1024, 3072);
    transpose_k<<<dim3(48, 32), tb>>>(proj_mouse_w, w4t, 1024, 1536);
    transpose_k<<<dim3(32, 48), tb>>>(wq_key, w5t, 1536, 1024);
    transpose_k<<<dim3(48, 32), tb>>>(proj_key_w, w6t, 1024, 1536);

    // conditioning path (tiny)
    gather_mouse<<<1, TT * 24>>>(mouse);
    kb_mlp<<<NF, 128>>>(kb, kb_w1, kb_b1, kb_w2, kb_b2);
    kv_gemm<<<TT, 256>>>(wkv_key);
    rmsrope_vec<<<dim3(NHEAD, TT), 32>>>(p_kv, kn_key, 2048, 0);

    const int MB = LTOK / 128;  // 192

    // GEMM1: [x | gm] @ mm_w1 + b1, gelu  (K=1560, split at 1536)
    tgemm<<<dim3(HID / 128, MB), 256, GEMM_SMEM>>>(x, CDIM, CDIM, p_gm, w1t, 1560, p_h1,
                                                   mm_b1, nullptr, LTOK, HID, 1560, 1);
    // GEMM2: h1 @ mm_w2 + b2
    tgemm<<<dim3(HID / 128, MB), 256, GEMM_SMEM>>>(p_h1, HID, HID, nullptr, w2t, HID, p_h2,
                                                   mm_b2, nullptr, LTOK, HID, HID, 0);
    ln_kernel<<<LTOK, 256>>>(p_h2, ln_g, ln_b);

    // GEMM3: qkv
    tgemm<<<dim3(3 * HID / 128, MB), 256, GEMM_SMEM>>>(p_h2, HID, HID, nullptr, w3t, HID, p_qkv,
                                                       nullptr, nullptr, LTOK, 3 * HID, HID, 0);
    attn1<<<(SSP * NHEAD * TT) / 8, 256>>>(p_qkv, p_o, qn_img, kn_img);

    // GEMM4: hidden = x + o @ proj_mouse_w
    tgemm<<<dim3(CDIM / 128, MB), 256, GEMM_SMEM>>>(p_o, HID, HID, nullptr, w4t, HID, p_hidden,
                                                    nullptr, x, LTOK, CDIM, HID, 2);
    // GEMM5: qh = hidden @ wq_key
    tgemm<<<dim3(HID / 128, MB), 256, GEMM_SMEM>>>(p_hidden, CDIM, CDIM, nullptr, w5t, CDIM, p_qh,
                                                   nullptr, nullptr, LTOK, HID, CDIM, 0);
    attn2<<<(LTOK * NHEAD) / 8, 256>>>(p_qh, p_kv, p_o, qn_key);

    // GEMM6: out = hidden + o2 @ proj_key_w
    tgemm<<<dim3(CDIM / 128, MB), 256, GEMM_SMEM>>>(p_o, HID, HID, nullptr, w6t, HID, (float*)d_out,
                                                    nullptr, p_hidden, LTOK, CDIM, HID, 2);
}

// round 5
// speedup vs baseline: 3.1268x; 1.0085x over previous
#include <cuda_runtime.h>
#include <math.h>
#include <stdint.h>

#define LTOK 24576
#define SSP  1024
#define TT   24
#define CDIM 1536
#define HID  1024
#define NHEAD 16
#define NF   104

// ---------------- scratch (device globals; allocation-free rule) ----------------
__device__ __align__(128) float g_kc[NF * 128];
__device__ __align__(128) float g_gm[TT * 24];
__device__ __align__(128) float g_kv[TT * 2048];
__device__ __align__(128) float g_h1[(size_t)LTOK * HID];
__device__ __align__(128) float g_h2[(size_t)LTOK * HID];
__device__ __align__(128) float g_qkv[(size_t)LTOK * 3 * HID];
__device__ __align__(128) float g_o[(size_t)LTOK * HID];
__device__ __align__(128) float g_hidden[(size_t)LTOK * CDIM];
__device__ __align__(128) float g_qh[(size_t)LTOK * HID];
// transposed weights [N][K]
__device__ __align__(128) float g_wt1[1024 * 1560];
__device__ __align__(128) float g_wt2[1024 * 1024];
__device__ __align__(128) float g_wt3[3072 * 1024];
__device__ __align__(128) float g_wt4[1536 * 1024];
__device__ __align__(128) float g_wt5[1024 * 1536];
__device__ __align__(128) float g_wt6[1536 * 1024];

// ---------------- fused weight transpose (all 6 in one launch) ----------------
struct TPack {
    const float* src[6];
    float* dst[6];
    int R[6];
    int C[6];
};

__global__ void transpose_all(TPack p)
{
    __shared__ float t[32][33];
    int z = blockIdx.z;
    int R = p.R[z], C = p.C[z];
    int c0 = blockIdx.x * 32, r0 = blockIdx.y * 32;
    if (c0 >= C || r0 >= R) return;
    const float* in = p.src[z];
    float* out = p.dst[z];
    int x = threadIdx.x, y = threadIdx.y;  // 32 x 8
#pragma unroll
    for (int i = 0; i < 32; i += 8) {
        int r = r0 + y + i, c = c0 + x;
        t[y + i][x] = (r < R && c < C) ? in[(size_t)r * C + c] : 0.f;
    }
    __syncthreads();
#pragma unroll
    for (int i = 0; i < 32; i += 8) {
        int r = c0 + y + i, c = r0 + x;  // out is [C][R]
        if (r < C && c < R) out[(size_t)r * R + c] = t[x][y + i];
    }
}

// ---------------- TF32 tensor-core GEMM: 128x256 tile, cp.async 3-stage + ldmatrix ----------------
#define STAGES 3
#define STBYTES 49152            // per stage: A 16KB + B 32KB
#define GEMM_SMEM (STAGES * STBYTES)

__device__ __forceinline__ void mma8(float* c, uint32_t a0, uint32_t a1, uint32_t a2,
                                     uint32_t a3, uint32_t b0, uint32_t b1) {
    asm volatile(
        "mma.sync.aligned.m16n8k8.row.col.f32.tf32.tf32.f32 "
        "{%0,%1,%2,%3}, {%4,%5,%6,%7}, {%8,%9}, {%0,%1,%2,%3};"
        : "+f"(c[0]), "+f"(c[1]), "+f"(c[2]), "+f"(c[3])
        : "r"(a0), "r"(a1), "r"(a2), "r"(a3), "r"(b0), "r"(b1));
}

#define LDSM4(P, ADDR)                                                   \
    asm volatile("ldmatrix.sync.aligned.m8n8.x4.b16 {%0,%1,%2,%3}, [%4];" \
                 : "=r"((P)[0]), "=r"((P)[1]), "=r"((P)[2]), "=r"((P)[3]) \
                 : "r"(ADDR))

__device__ __forceinline__ void cpa16(uint32_t dst, const void* src, int sz) {
    asm volatile("cp.async.cg.shared.global [%0], [%1], 16, %2;\n"
                 :: "r"(dst), "l"(src), "r"(sz));
}

__device__ __forceinline__ float gelu_fast(float v) {
    float u2 = 1.5957691216057308f * (v + 0.044715f * v * v * v);  // 2 * 0.79788456 * (...)
    return __fdividef(v, 1.f + __expf(-u2));
}

__global__ void __launch_bounds__(256, 1) tgemm(
    const float* __restrict__ A, int lda, int Ksplit, const float* __restrict__ A2,
    const float* __restrict__ Bt, int ldb,
    float* __restrict__ Cout,
    const float* __restrict__ bias,
    const float* __restrict__ addsrc,
    int M, int N, int K, int epi)
{
    extern __shared__ float smem[];
    const int tid = threadIdx.x, lane = tid & 31, warp = tid >> 5;
    const int wm = warp & 1, wn = warp >> 1;            // 2x4 warps -> 64x64 tiles
    const int rowBase = blockIdx.y * 128, colBase = blockIdx.x * 256;
    const int nk = (K + 31) >> 5;
    uint32_t sbase = (uint32_t)__cvta_generic_to_shared(smem);

    // loader: thread handles k-unit u of A rows arow+32i (i<4) and B rows arow+32j (j<8)
    const int arow = tid >> 3;
    const int u = tid & 7;
    const uint32_t swz = (uint32_t)(arow * 128 + ((u ^ (arow & 7)) << 4));
    const uint32_t dstA0 = sbase + swz;
    const uint32_t dstB0 = sbase + 16384 + swz;

    // compute-side constants
    const int mtx = lane >> 3, rl = lane & 7;
    const int rA = wm * 64 + ((mtx >> 1) << 3) + rl;
    const int rB = wn * 64 + ((mtx >> 1) << 3) + rl;
    const int usel = mtx & 1;
    const int axor = rA & 7, bxor = rB & 7;
    const uint32_t aoff = (uint32_t)(rA * 128);
    const uint32_t boff = (uint32_t)(16384 + rB * 128);

    float acc[4][8][4];
#pragma unroll
    for (int a = 0; a < 4; a++)
#pragma unroll
        for (int b = 0; b < 8; b++)
#pragma unroll
            for (int c = 0; c < 4; c++) acc[a][b][c] = 0.f;

#define ISSUE(KT, STG)                                                        \
    {                                                                         \
        int kw = (KT) * 32 + u * 4;                                           \
        uint32_t sA = dstA0 + (STG) * STBYTES;                                \
        uint32_t sB = dstB0 + (STG) * STBYTES;                                \
        _Pragma("unroll")                                                     \
        for (int i = 0; i < 4; i++) {                                         \
            int r = arow + 32 * i;                                            \
            const float* srcA; int pA = 16;                                   \
            if (kw + 4 <= Ksplit)                                             \
                srcA = A + (size_t)(rowBase + r) * lda + kw;                  \
            else if (kw + 4 <= K)                                             \
                srcA = A2 + ((rowBase + r) >> 10) * 24 + (kw - Ksplit);       \
            else { srcA = A; pA = 0; }                                        \
            cpa16(sA + i * 4096, srcA, pA);                                   \
        }                                                                     \
        _Pragma("unroll")                                                     \
        for (int j = 0; j < 8; j++) {                                         \
            int r = arow + 32 * j;                                            \
            const float* srcB; int pB = 16;                                   \
            if (kw + 4 <= K)                                                  \
                srcB = Bt + (size_t)(colBase + r) * ldb + kw;                 \
            else { srcB = Bt; pB = 0; }                                       \
            cpa16(sB + j * 4096, srcB, pB);                                   \
        }                                                                     \
        asm volatile("cp.async.commit_group;\n");                             \
    }

#define COMPUTE(STG)                                                          \
    {                                                                         \
        uint32_t sb = sbase + (STG) * STBYTES;                                \
        _Pragma("unroll")                                                     \
        for (int kk = 0; kk < 4; kk++) {                                      \
            uint32_t ua = (uint32_t)(((2 * kk + usel) ^ axor) << 4);          \
            uint32_t ub = (uint32_t)(((2 * kk + usel) ^ bxor) << 4);          \
            uint32_t afr[4][4], bfr[4][4];                                    \
            _Pragma("unroll")                                                 \
            for (int mt = 0; mt < 4; mt++)                                    \
                LDSM4(afr[mt], sb + aoff + ua + mt * 2048);                   \
            _Pragma("unroll")                                                 \
            for (int p = 0; p < 4; p++)                                       \
                LDSM4(bfr[p], sb + boff + ub + p * 2048);                     \
            _Pragma("unroll")                                                 \
            for (int mt = 0; mt < 4; mt++)                                    \
                _Pragma("unroll")                                             \
                for (int nt = 0; nt < 8; nt++)                                \
                    mma8(acc[mt][nt],                                         \
                         afr[mt][0], afr[mt][2], afr[mt][1], afr[mt][3],      \
                         bfr[nt >> 1][(nt & 1) * 2], bfr[nt >> 1][(nt & 1) * 2 + 1]); \
        }                                                                     \
    }

    ISSUE(0, 0);
    ISSUE(1, 1);
    for (int t = 0; t < nk; t++) {
        asm volatile("cp.async.wait_group %0;\n" :: "n"(STAGES - 2));
        __syncthreads();
        int pf = t + STAGES - 1;
        if (pf < nk) { ISSUE(pf, pf % STAGES); }
        else { asm volatile("cp.async.commit_group;\n"); }
        COMPUTE(t % STAGES);
    }

    // epilogue
#pragma unroll
    for (int mt = 0; mt < 4; mt++) {
#pragma unroll
        for (int nt = 0; nt < 8; nt++) {
            int col = colBase + wn * 64 + nt * 8 + (lane & 3) * 2;
#pragma unroll
            for (int half = 0; half < 2; half++) {
                int row = rowBase + wm * 64 + mt * 16 + (lane >> 2) + half * 8;
                float v0 = acc[mt][nt][half * 2 + 0];
                float v1 = acc[mt][nt][half * 2 + 1];
                if (bias) { v0 += bias[col]; v1 += bias[col + 1]; }
                if (epi == 1) {
                    v0 = gelu_fast(v0);
                    v1 = gelu_fast(v1);
                } else if (epi == 2) {
                    float2 a = *(const float2*)(addsrc + (size_t)row * N + col);
                    v0 += a.x; v1 += a.y;
                }
                float2 o; o.x = v0; o.y = v1;
                *(float2*)(Cout + (size_t)row * N + col) = o;
            }
        }
    }
#undef ISSUE
#undef COMPUTE
}

// ---------------- LayerNorm over HID=1024, in place ----------------
__global__ void __launch_bounds__(256) ln_kernel(float* __restrict__ h,
                                                 const float* __restrict__ g,
                                                 const float* __restrict__ b)
{
    __shared__ float row[1024];
    __shared__ float red[8];
    __shared__ float meanv, rstdv;
    int r = blockIdx.x;
    float* hp = h + (size_t)r * 1024;
    int tid = threadIdx.x;
    float s = 0.f;
    for (int i = tid; i < 1024; i += 256) { float v = hp[i]; row[i] = v; s += v; }
    for (int o = 16; o; o >>= 1) s += __shfl_xor_sync(~0u, s, o);
    if ((tid & 31) == 0) red[tid >> 5] = s;
    __syncthreads();
    if (tid == 0) { float t = 0; for (int i = 0; i < 8; i++) t += red[i]; meanv = t * (1.f / 1024.f); }
    __syncthreads();
    float m = meanv;
    float ss = 0.f;
    for (int i = tid; i < 1024; i += 256) { float d = row[i] - m; ss += d * d; }
    for (int o = 16; o; o >>= 1) ss += __shfl_xor_sync(~0u, ss, o);
    if ((tid & 31) == 0) red[tid >> 5] = ss;
    __syncthreads();
    if (tid == 0) { float t = 0; for (int i = 0; i < 8; i++) t += red[i]; rstdv = rsqrtf(t * (1.f / 1024.f) + 1e-5f); }
    __syncthreads();
    float rs = rstdv;
    for (int i = tid; i < 1024; i += 256) hp[i] = (row[i] - m) * rs * g[i] + b[i];
}

// ---------------- fused RMSNorm + RoPE (register-level, per warp row) ----------------
__device__ __forceinline__ void rmsrope_w(float& v0, float& v1,
                                          const float* __restrict__ w, int lane, int t)
{
    float ss = v0 * v0 + v1 * v1;
    for (int o = 16; o; o >>= 1) ss += __shfl_xor_sync(~0u, ss, o);
    float rs = rsqrtf(ss * (1.f / 64.f) + 1e-6f);
    v0 = v0 * rs * w[lane];
    v1 = v1 * rs * w[lane + 32];
    float other = __shfl_xor_sync(~0u, v0, 1);
    if (lane < 8) {
        float inv = exp2f(-2.f * (float)(lane >> 1));
        float ang = (float)t * inv;
        float c, s;
        sincosf(ang, &s, &c);
        float rot = (lane & 1) ? other : -other;
        v0 = v0 * c + rot * s;
    }
}

// ---------------- attn1: smem-tiled per (s, h), fused q/k rms+rope ----------------
// block = (s, h); loads k,v for all 24 frames into smem (k normed once).
__global__ void __launch_bounds__(256) attn1(const float* __restrict__ qkv,
                                             float* __restrict__ o,
                                             const float* __restrict__ qn,
                                             const float* __restrict__ kn)
{
    __shared__ float ks[24][64];
    __shared__ float vs[24][64];
    int s = blockIdx.x, h = blockIdx.y;
    int warp = threadIdx.x >> 5, lane = threadIdx.x & 31;

#pragma unroll
    for (int j = 0; j < 3; j++) {
        int t = warp * 3 + j;
        const float* base = qkv + (size_t)(t * 1024 + s) * 3072 + h * 64;
        float k0 = base[1024 + lane], k1 = base[1024 + lane + 32];
        rmsrope_w(k0, k1, kn, lane, t);
        ks[t][lane] = k0; ks[t][lane + 32] = k1;
        vs[t][lane] = base[2048 + lane];
        vs[t][lane + 32] = base[2048 + lane + 32];
    }
    __syncthreads();

#pragma unroll
    for (int j = 0; j < 3; j++) {
        int t = warp * 3 + j;
        const float* qp = qkv + (size_t)(t * 1024 + s) * 3072 + h * 64;
        float q0 = qp[lane], q1 = qp[lane + 32];
        rmsrope_w(q0, q1, qn, lane, t);
        int u0 = max(0, t - 5);
        int nu = t - u0 + 1;
        float sc[6];
        float mx = -1e30f;
#pragma unroll
        for (int i = 0; i < 6; i++) {
            if (i < nu) {
                int uu = u0 + i;
                float d = q0 * ks[uu][lane] + q1 * ks[uu][lane + 32];
                for (int off = 16; off; off >>= 1) d += __shfl_xor_sync(~0u, d, off);
                sc[i] = d * 0.125f;
                mx = fmaxf(mx, sc[i]);
            }
        }
        float denom = 0.f, a0 = 0.f, a1 = 0.f;
#pragma unroll
        for (int i = 0; i < 6; i++) {
            if (i < nu) {
                float p = __expf(sc[i] - mx);
                denom += p;
                int uu = u0 + i;
                a0 += p * vs[uu][lane]; a1 += p * vs[uu][lane + 32];
            }
        }
        float inv = 1.f / denom;
        float* op = o + (size_t)(t * 1024 + s) * 1024 + h * 64;
        op[lane] = a0 * inv; op[lane + 32] = a1 * inv;
    }
}

// ---------------- attn2: keyboard cross-attn, fused q rms+rope ----------------
__global__ void __launch_bounds__(256) attn2(const float* __restrict__ q,
                                             const float* __restrict__ kv,
                                             float* __restrict__ o,
                                             const float* __restrict__ qn)
{
    int item = blockIdx.x * 8 + (threadIdx.x >> 5);
    int lane = threadIdx.x & 31;
    int h = item & 15;
    int r = item >> 4;
    int t = r >> 10;
    int u0 = max(0, t - 5);
    int nu = t - u0 + 1;

    const float* qp = q + (size_t)r * 1024 + h * 64;
    float q0 = qp[lane], q1 = qp[lane + 32];
    rmsrope_w(q0, q1, qn, lane, t);

    float sc[6];
    float mx = -1e30f;
#pragma unroll
    for (int i = 0; i < 6; i++) {
        if (i < nu) {
            int uu = u0 + i;
            const float* kp = kv + (size_t)uu * 2048 + h * 64;
            float d = q0 * kp[lane] + q1 * kp[lane + 32];
            for (int off = 16; off; off >>= 1) d += __shfl_xor_sync(~0u, d, off);
            sc[i] = d * 0.125f;
            mx = fmaxf(mx, sc[i]);
        }
    }
    float denom = 0.f, a0 = 0.f, a1 = 0.f;
#pragma unroll
    for (int i = 0; i < 6; i++) {
        if (i < nu) {
            float p = __expf(sc[i] - mx);
            denom += p;
            int uu = u0 + i;
            const float* vp = kv + (size_t)uu * 2048 + 1024 + h * 64;
            a0 += p * vp[lane]; a1 += p * vp[lane + 32];
        }
    }
    float inv = 1.f / denom;
    float* op = o + (size_t)r * 1024 + h * 64;
    op[lane] = a0 * inv; op[lane + 32] = a1 * inv;
}

// ---------------- conditioning: keyboard MLP (+ mouse gather in block 0) ----------------
__global__ void kb_mlp(const float* __restrict__ kb,
                       const float* __restrict__ w1, const float* __restrict__ b1,
                       const float* __restrict__ w2, const float* __restrict__ b2,
                       const float* __restrict__ mouse)
{
    int n = blockIdx.x;
    int c = threadIdx.x;  // 128
    if (n == 0) {
        for (int i = c; i < TT * 24; i += 128) {
            int t = i / 24, j2 = i % 24;
            g_gm[i] = mouse[(4 * t + (j2 >> 1)) * 2 + (j2 & 1)];
        }
    }
    __shared__ float hid[128];
    float a = b1[c];
#pragma unroll
    for (int i = 0; i < 6; i++) a += kb[n * 6 + i] * w1[i * 128 + c];
    hid[c] = a / (1.f + __expf(-a));
    __syncthreads();
    float ov = b2[c];
    for (int i = 0; i < 128; i++) ov += hid[i] * w2[i * 128 + c];
    g_kc[n * 128 + c] = ov;
}

// ---------------- conditioning: kv projection + k rms+rope fused ----------------
__global__ void kv_gemm(const float* __restrict__ wkv, const float* __restrict__ knw)
{
    int t = blockIdx.x;
    __shared__ float gk[1536];
    __shared__ float out[2048];
    for (int i = threadIdx.x; i < 1536; i += 256)
        gk[i] = g_kc[(4 * t + i / 128) * 128 + (i & 127)];
    __syncthreads();
    for (int oc = threadIdx.x; oc < 2048; oc += 256) {
        float a = 0.f;
        for (int i = 0; i < 1536; i++) a += gk[i] * wkv[(size_t)i * 2048 + oc];
        out[oc] = a;
    }
    __syncthreads();
    // rms+rope on k half (first 1024 = 16 heads x 64)
    int warp = threadIdx.x >> 5, lane = threadIdx.x & 31;
#pragma unroll
    for (int hh = 0; hh < 2; hh++) {
        int h = warp * 2 + hh;
        float v0 = out[h * 64 + lane], v1 = out[h * 64 + lane + 32];
        rmsrope_w(v0, v1, knw, lane, t);
        out[h * 64 + lane] = v0; out[h * 64 + lane + 32] = v1;
    }
    __syncthreads();
    for (int i = threadIdx.x; i < 2048; i += 256)
        g_kv[t * 2048 + i] = out[i];
}

// ---------------- host ----------------
extern "C" void kernel_launch(void* const* d_in, const int* in_sizes, int n_in,
                              void* d_out, int out_size)
{
    int wb = (in_sizes[3] == 1) ? 6 : 3;
    const float* x       = (const float*)d_in[0];
    const float* mouse   = (const float*)d_in[1];
    const float* kb      = (const float*)d_in[2];
    const float* kb_w1   = (const float*)d_in[wb + 0];
    const float* kb_b1   = (const float*)d_in[wb + 1];
    const float* kb_w2   = (const float*)d_in[wb + 2];
    const float* kb_b2   = (const float*)d_in[wb + 3];
    const float* mm_w1   = (const float*)d_in[wb + 4];
    const float* mm_b1   = (const float*)d_in[wb + 5];
    const float* mm_w2   = (const float*)d_in[wb + 6];
    const float* mm_b2   = (const float*)d_in[wb + 7];
    const float* ln_g    = (const float*)d_in[wb + 8];
    const float* ln_b    = (const float*)d_in[wb + 9];
    const float* qkv_w   = (const float*)d_in[wb + 10];
    const float* qn_img  = (const float*)d_in[wb + 11];
    const float* kn_img  = (const float*)d_in[wb + 12];
    const float* qn_key  = (const float*)d_in[wb + 13];
    const float* kn_key  = (const float*)d_in[wb + 14];
    const float* proj_mouse_w = (const float*)d_in[wb + 15];
    const float* wq_key  = (const float*)d_in[wb + 16];
    const float* wkv_key = (const float*)d_in[wb + 17];
    const float* proj_key_w   = (const float*)d_in[wb + 18];

    float *p_kv, *p_h1, *p_h2, *p_qkv, *p_o, *p_hidden, *p_qh, *p_gm;
    float *w1t, *w2t, *w3t, *w4t, *w5t, *w6t;
    cudaGetSymbolAddress((void**)&p_gm, g_gm);
    cudaGetSymbolAddress((void**)&p_kv, g_kv);
    cudaGetSymbolAddress((void**)&p_h1, g_h1);
    cudaGetSymbolAddress((void**)&p_h2, g_h2);
    cudaGetSymbolAddress((void**)&p_qkv, g_qkv);
    cudaGetSymbolAddress((void**)&p_o, g_o);
    cudaGetSymbolAddress((void**)&p_hidden, g_hidden);
    cudaGetSymbolAddress((void**)&p_qh, g_qh);
    cudaGetSymbolAddress((void**)&w1t, g_wt1);
    cudaGetSymbolAddress((void**)&w2t, g_wt2);
    cudaGetSymbolAddress((void**)&w3t, g_wt3);
    cudaGetSymbolAddress((void**)&w4t, g_wt4);
    cudaGetSymbolAddress((void**)&w5t, g_wt5);
    cudaGetSymbolAddress((void**)&w6t, g_wt6);

    cudaFuncSetAttribute(tgemm, cudaFuncAttributeMaxDynamicSharedMemorySize, GEMM_SMEM);

    // one fused transpose launch for all six weights
    TPack tp;
    tp.src[0] = mm_w1;        tp.dst[0] = w1t; tp.R[0] = 1560; tp.C[0] = 1024;
    tp.src[1] = mm_w2;        tp.dst[1] = w2t; tp.R[1] = 1024; tp.C[1] = 1024;
    tp.src[2] = qkv_w;        tp.dst[2] = w3t; tp.R[2] = 1024; tp.C[2] = 3072;
    tp.src[3] = proj_mouse_w; tp.dst[3] = w4t; tp.R[3] = 1024; tp.C[3] = 1536;
    tp.src[4] = wq_key;       tp.dst[4] = w5t; tp.R[4] = 1536; tp.C[4] = 1024;
    tp.src[5] = proj_key_w;   tp.dst[5] = w6t; tp.R[5] = 1024; tp.C[5] = 1536;
    transpose_all<<<dim3(96, 49, 6), dim3(32, 8)>>>(tp);

    // conditioning path
    kb_mlp<<<NF, 128>>>(kb, kb_w1, kb_b1, kb_w2, kb_b2, mouse);
    kv_gemm<<<TT, 256>>>(wkv_key, kn_key);

    const int MB = LTOK / 128;  // 192

    // GEMM1: [x | gm] @ mm_w1 + b1, gelu  (K=1560, split at 1536)
    tgemm<<<dim3(HID / 256, MB), 256, GEMM_SMEM>>>(x, CDIM, CDIM, p_gm, w1t, 1560, p_h1,
                                                   mm_b1, nullptr, LTOK, HID, 1560, 1);
    // GEMM2: h1 @ mm_w2 + b2
    tgemm<<<dim3(HID / 256, MB), 256, GEMM_SMEM>>>(p_h1, HID, HID, nullptr, w2t, HID, p_h2,
                                                   mm_b2, nullptr, LTOK, HID, HID, 0);
    ln_kernel<<<LTOK, 256>>>(p_h2, ln_g, ln_b);

    // GEMM3: qkv
    tgemm<<<dim3(3 * HID / 256, MB), 256, GEMM_SMEM>>>(p_h2, HID, HID, nullptr, w3t, HID, p_qkv,
                                                       nullptr, nullptr, LTOK, 3 * HID, HID, 0);
    attn1<<<dim3(SSP, NHEAD), 256>>>(p_qkv, p_o, qn_img, kn_img);

    // GEMM4: hidden = x + o @ proj_mouse_w
    tgemm<<<dim3(CDIM / 256, MB), 256, GEMM_SMEM>>>(p_o, HID, HID, nullptr, w4t, HID, p_hidden,
                                                    nullptr, x, LTOK, CDIM, HID, 2);
    // GEMM5: qh = hidden @ wq_key
    tgemm<<<dim3(HID / 256, MB), 256, GEMM_SMEM>>>(p_hidden, CDIM, CDIM, nullptr, w5t, CDIM, p_qh,
                                                   nullptr, nullptr, LTOK, HID, CDIM, 0);
    attn2<<<(LTOK * NHEAD) / 8, 256>>>(p_qh, p_kv, p_o, qn_key);

    // GEMM6: out = hidden + o2 @ proj_key_w
    tgemm<<<dim3(CDIM / 256, MB), 256, GEMM_SMEM>>>(p_o, HID, HID, nullptr, w6t, HID, (float*)d_out,
                                                    nullptr, p_hidden, LTOK, CDIM, HID, 2);
}

// round 6
// speedup vs baseline: 3.3358x; 1.0668x over previous
#include <cuda_runtime.h>
#include <math.h>
#include <stdint.h>

#define LTOK 24576
#define SSP  1024
#define TT   24
#define CDIM 1536
#define HID  1024
#define NHEAD 16
#define NF   104

// ---------------- scratch (device globals; allocation-free rule) ----------------
__device__ __align__(128) float g_kc[NF * 128];
__device__ __align__(128) float g_gm[TT * 24];
__device__ __align__(128) float g_mext[TT * 1024];
__device__ __align__(128) float g_kv[TT * 2048];
__device__ __align__(128) float g_h1[(size_t)LTOK * HID];
__device__ __align__(128) float g_h2[(size_t)LTOK * HID];
__device__ __align__(128) float g_qkv[(size_t)LTOK * 3 * HID];
__device__ __align__(128) float g_o[(size_t)LTOK * HID];
__device__ __align__(128) float g_hidden[(size_t)LTOK * CDIM];
__device__ __align__(128) float g_qh[(size_t)LTOK * HID];
// transposed weights [N][K]
__device__ __align__(128) float g_wt1[1024 * 1560];
__device__ __align__(128) float g_wt2[1024 * 1024];
__device__ __align__(128) float g_wt3[3072 * 1024];
__device__ __align__(128) float g_wt4[1536 * 1024];
__device__ __align__(128) float g_wt5[1024 * 1536];
__device__ __align__(128) float g_wt6[1536 * 1024];

// ---------------- fused weight transpose (all 6 in one launch) ----------------
struct TPack {
    const float* src[6];
    float* dst[6];
    int R[6];
    int C[6];
};

__global__ void transpose_all(TPack p)
{
    __shared__ float t[32][33];
    int z = blockIdx.z;
    int R = p.R[z], C = p.C[z];
    int c0 = blockIdx.x * 32, r0 = blockIdx.y * 32;
    if (c0 >= C || r0 >= R) return;
    const float* in = p.src[z];
    float* out = p.dst[z];
    int x = threadIdx.x, y = threadIdx.y;  // 32 x 8
#pragma unroll
    for (int i = 0; i < 32; i += 8) {
        int r = r0 + y + i, c = c0 + x;
        t[y + i][x] = (r < R && c < C) ? in[(size_t)r * C + c] : 0.f;
    }
    __syncthreads();
#pragma unroll
    for (int i = 0; i < 32; i += 8) {
        int r = c0 + y + i, c = r0 + x;  // out is [C][R]
        if (r < C && c < R) out[(size_t)r * R + c] = t[x][y + i];
    }
}

// ---------------- mouse rank-24 contribution: mext[t][col] = sum_k gm[t][k] * w1t[col][1536+k]
__global__ void mext_kernel(const float* __restrict__ w1t)
{
    int t = blockIdx.x;
    __shared__ float gm[24];
    if (threadIdx.x < 24) gm[threadIdx.x] = g_gm[t * 24 + threadIdx.x];
    __syncthreads();
    for (int col = threadIdx.x; col < 1024; col += 256) {
        const float* wp = w1t + (size_t)col * 1560 + 1536;
        float s = 0.f;
#pragma unroll
        for (int k = 0; k < 24; k++) s += gm[k] * wp[k];
        g_mext[t * 1024 + col] = s;
    }
}

// ---------------- TF32 tensor-core GEMM: 128x256 tile, cp.async 4-stage + ldmatrix ----------------
#define STAGES 4
#define STBYTES 49152            // per stage: A 16KB + B 32KB
#define GEMM_SMEM (STAGES * STBYTES)

__device__ __forceinline__ void mma8(float* c, uint32_t a0, uint32_t a1, uint32_t a2,
                                     uint32_t a3, uint32_t b0, uint32_t b1) {
    asm volatile(
        "mma.sync.aligned.m16n8k8.row.col.f32.tf32.tf32.f32 "
        "{%0,%1,%2,%3}, {%4,%5,%6,%7}, {%8,%9}, {%0,%1,%2,%3};"
        : "+f"(c[0]), "+f"(c[1]), "+f"(c[2]), "+f"(c[3])
        : "r"(a0), "r"(a1), "r"(a2), "r"(a3), "r"(b0), "r"(b1));
}

#define LDSM4(P, ADDR)                                                   \
    asm volatile("ldmatrix.sync.aligned.m8n8.x4.b16 {%0,%1,%2,%3}, [%4];" \
                 : "=r"((P)[0]), "=r"((P)[1]), "=r"((P)[2]), "=r"((P)[3]) \
                 : "r"(ADDR))

__device__ __forceinline__ void cpa16(uint32_t dst, const float* src) {
    asm volatile("cp.async.cg.shared.global [%0], [%1], 16;\n"
                 :: "r"(dst), "l"(src));
}

__device__ __forceinline__ float gelu_fast(float v) {
    float u2 = 1.5957691216057308f * (v + 0.044715f * v * v * v);
    return __fdividef(v, 1.f + __expf(-u2));
}

// K % 32 == 0, N % 256 == 0, M % 128 == 0 — no guards anywhere.
// epi: 0 = bias(optional), 1 = bias+gelu (+extra per-frame row add), 2 = residual add
__global__ void __launch_bounds__(256, 1) tgemm(
    const float* __restrict__ A, int lda,
    const float* __restrict__ Bt, int ldb,
    float* __restrict__ Cout,
    const float* __restrict__ bias,
    const float* __restrict__ addsrc,
    const float* __restrict__ extra,
    int N, int K, int epi)
{
    extern __shared__ float smem[];
    const int tid = threadIdx.x, lane = tid & 31, warp = tid >> 5;
    const int wm = warp & 1, wn = warp >> 1;            // 2x4 warps -> 64x64 tiles
    const int rowBase = blockIdx.y * 128, colBase = blockIdx.x * 256;
    const int nk = K >> 5;
    uint32_t sbase = (uint32_t)__cvta_generic_to_shared(smem);

    // loader: thread handles k-unit u (4 floats) of A rows arow+32i (i<4) and B rows arow+32j (j<8)
    const int arow = tid >> 3;
    const int u = tid & 7;
    const uint32_t swz = (uint32_t)(arow * 128 + ((u ^ (arow & 7)) << 4));
    const uint32_t dstA0 = sbase + swz;
    const uint32_t dstB0 = sbase + 16384 + swz;

    const float* pa[4];
    const float* pb[8];
#pragma unroll
    for (int i = 0; i < 4; i++)
        pa[i] = A + (size_t)(rowBase + arow + 32 * i) * lda + u * 4;
#pragma unroll
    for (int j = 0; j < 8; j++)
        pb[j] = Bt + (size_t)(colBase + arow + 32 * j) * ldb + u * 4;

    // compute-side constants
    const int mtx = lane >> 3, rl = lane & 7;
    const int rA = wm * 64 + ((mtx >> 1) << 3) + rl;
    const int rB = wn * 64 + ((mtx >> 1) << 3) + rl;
    const int usel = mtx & 1;
    const int axor = rA & 7, bxor = rB & 7;
    const uint32_t aoff = (uint32_t)(rA * 128);
    const uint32_t boff = (uint32_t)(16384 + rB * 128);

    float acc[4][8][4];
#pragma unroll
    for (int a = 0; a < 4; a++)
#pragma unroll
        for (int b = 0; b < 8; b++)
#pragma unroll
            for (int c = 0; c < 4; c++) acc[a][b][c] = 0.f;

#define ISSUE(STG)                                                            \
    {                                                                         \
        uint32_t sA = dstA0 + (STG) * STBYTES;                                \
        uint32_t sB = dstB0 + (STG) * STBYTES;                                \
        _Pragma("unroll")                                                     \
        for (int i = 0; i < 4; i++) { cpa16(sA + i * 4096, pa[i]); pa[i] += 32; } \
        _Pragma("unroll")                                                     \
        for (int j = 0; j < 8; j++) { cpa16(sB + j * 4096, pb[j]); pb[j] += 32; } \
        asm volatile("cp.async.commit_group;\n");                             \
    }

#define COMPUTE(STG)                                                          \
    {                                                                         \
        uint32_t sb = sbase + (STG) * STBYTES;                                \
        _Pragma("unroll")                                                     \
        for (int kk = 0; kk < 4; kk++) {                                      \
            uint32_t ua = (uint32_t)(((2 * kk + usel) ^ axor) << 4);          \
            uint32_t ub = (uint32_t)(((2 * kk + usel) ^ bxor) << 4);          \
            uint32_t afr[4][4], bfr[4][4];                                    \
            _Pragma("unroll")                                                 \
            for (int mt = 0; mt < 4; mt++)                                    \
                LDSM4(afr[mt], sb + aoff + ua + mt * 2048);                   \
            _Pragma("unroll")                                                 \
            for (int p = 0; p < 4; p++)                                       \
                LDSM4(bfr[p], sb + boff + ub + p * 2048);                     \
            _Pragma("unroll")                                                 \
            for (int mt = 0; mt < 4; mt++)                                    \
                _Pragma("unroll")                                             \
                for (int nt = 0; nt < 8; nt++)                                \
                    mma8(acc[mt][nt],                                         \
                         afr[mt][0], afr[mt][2], afr[mt][1], afr[mt][3],      \
                         bfr[nt >> 1][(nt & 1) * 2], bfr[nt >> 1][(nt & 1) * 2 + 1]); \
        }                                                                     \
    }

    ISSUE(0);
    ISSUE(1);
    ISSUE(2);
    for (int t = 0; t < nk; t++) {
        asm volatile("cp.async.wait_group %0;\n" :: "n"(STAGES - 2));
        __syncthreads();
        int pf = t + STAGES - 1;
        if (pf < nk) { ISSUE(pf & 3); }
        else { asm volatile("cp.async.commit_group;\n"); }
        COMPUTE(t & 3);
    }

    // epilogue
#pragma unroll
    for (int mt = 0; mt < 4; mt++) {
#pragma unroll
        for (int nt = 0; nt < 8; nt++) {
            int col = colBase + wn * 64 + nt * 8 + (lane & 3) * 2;
#pragma unroll
            for (int half = 0; half < 2; half++) {
                int row = rowBase + wm * 64 + mt * 16 + (lane >> 2) + half * 8;
                float v0 = acc[mt][nt][half * 2 + 0];
                float v1 = acc[mt][nt][half * 2 + 1];
                if (bias) { v0 += bias[col]; v1 += bias[col + 1]; }
                if (epi == 1) {
                    const float* ep = extra + (size_t)(row >> 10) * N + col;
                    v0 = gelu_fast(v0 + ep[0]);
                    v1 = gelu_fast(v1 + ep[1]);
                } else if (epi == 2) {
                    float2 a = *(const float2*)(addsrc + (size_t)row * N + col);
                    v0 += a.x; v1 += a.y;
                }
                float2 o; o.x = v0; o.y = v1;
                *(float2*)(Cout + (size_t)row * N + col) = o;
            }
        }
    }
#undef ISSUE
#undef COMPUTE
}

// ---------------- LayerNorm over HID=1024, in place ----------------
__global__ void __launch_bounds__(256) ln_kernel(float* __restrict__ h,
                                                 const float* __restrict__ g,
                                                 const float* __restrict__ b)
{
    __shared__ float row[1024];
    __shared__ float red[8];
    __shared__ float meanv, rstdv;
    int r = blockIdx.x;
    float* hp = h + (size_t)r * 1024;
    int tid = threadIdx.x;
    float s = 0.f;
    for (int i = tid; i < 1024; i += 256) { float v = hp[i]; row[i] = v; s += v; }
    for (int o = 16; o; o >>= 1) s += __shfl_xor_sync(~0u, s, o);
    if ((tid & 31) == 0) red[tid >> 5] = s;
    __syncthreads();
    if (tid == 0) { float t = 0; for (int i = 0; i < 8; i++) t += red[i]; meanv = t * (1.f / 1024.f); }
    __syncthreads();
    float m = meanv;
    float ss = 0.f;
    for (int i = tid; i < 1024; i += 256) { float d = row[i] - m; ss += d * d; }
    for (int o = 16; o; o >>= 1) ss += __shfl_xor_sync(~0u, ss, o);
    if ((tid & 31) == 0) red[tid >> 5] = ss;
    __syncthreads();
    if (tid == 0) { float t = 0; for (int i = 0; i < 8; i++) t += red[i]; rstdv = rsqrtf(t * (1.f / 1024.f) + 1e-5f); }
    __syncthreads();
    float rs = rstdv;
    for (int i = tid; i < 1024; i += 256) hp[i] = (row[i] - m) * rs * g[i] + b[i];
}

// ---------------- fused RMSNorm + RoPE (register-level, per warp row) ----------------
__device__ __forceinline__ void rmsrope_w(float& v0, float& v1,
                                          const float* __restrict__ w, int lane, int t)
{
    float ss = v0 * v0 + v1 * v1;
    for (int o = 16; o; o >>= 1) ss += __shfl_xor_sync(~0u, ss, o);
    float rs = rsqrtf(ss * (1.f / 64.f) + 1e-6f);
    v0 = v0 * rs * w[lane];
    v1 = v1 * rs * w[lane + 32];
    float other = __shfl_xor_sync(~0u, v0, 1);
    if (lane < 8) {
        float inv = exp2f(-2.f * (float)(lane >> 1));
        float ang = (float)t * inv;
        float c, s;
        sincosf(ang, &s, &c);
        float rot = (lane & 1) ? other : -other;
        v0 = v0 * c + rot * s;
    }
}

// ---------------- attn1: smem-tiled per (s, h), fused q/k rms+rope ----------------
__global__ void __launch_bounds__(256) attn1(const float* __restrict__ qkv,
                                             float* __restrict__ o,
                                             const float* __restrict__ qn,
                                             const float* __restrict__ kn)
{
    __shared__ float ks[24][64];
    __shared__ float vs[24][64];
    int s = blockIdx.x, h = blockIdx.y;
    int warp = threadIdx.x >> 5, lane = threadIdx.x & 31;

#pragma unroll
    for (int j = 0; j < 3; j++) {
        int t = warp * 3 + j;
        const float* base = qkv + (size_t)(t * 1024 + s) * 3072 + h * 64;
        float k0 = base[1024 + lane], k1 = base[1024 + lane + 32];
        rmsrope_w(k0, k1, kn, lane, t);
        ks[t][lane] = k0; ks[t][lane + 32] = k1;
        vs[t][lane] = base[2048 + lane];
        vs[t][lane + 32] = base[2048 + lane + 32];
    }
    __syncthreads();

#pragma unroll
    for (int j = 0; j < 3; j++) {
        int t = warp * 3 + j;
        const float* qp = qkv + (size_t)(t * 1024 + s) * 3072 + h * 64;
        float q0 = qp[lane], q1 = qp[lane + 32];
        rmsrope_w(q0, q1, qn, lane, t);
        int u0 = max(0, t - 5);
        int nu = t - u0 + 1;
        float sc[6];
        float mx = -1e30f;
#pragma unroll
        for (int i = 0; i < 6; i++) {
            if (i < nu) {
                int uu = u0 + i;
                float d = q0 * ks[uu][lane] + q1 * ks[uu][lane + 32];
                for (int off = 16; off; off >>= 1) d += __shfl_xor_sync(~0u, d, off);
                sc[i] = d * 0.125f;
                mx = fmaxf(mx, sc[i]);
            }
        }
        float denom = 0.f, a0 = 0.f, a1 = 0.f;
#pragma unroll
        for (int i = 0; i < 6; i++) {
            if (i < nu) {
                float p = __expf(sc[i] - mx);
                denom += p;
                int uu = u0 + i;
                a0 += p * vs[uu][lane]; a1 += p * vs[uu][lane + 32];
            }
        }
        float inv = 1.f / denom;
        float* op = o + (size_t)(t * 1024 + s) * 1024 + h * 64;
        op[lane] = a0 * inv; op[lane + 32] = a1 * inv;
    }
}

// ---------------- attn2: keyboard cross-attn, fused q rms+rope ----------------
__global__ void __launch_bounds__(256) attn2(const float* __restrict__ q,
                                             const float* __restrict__ kv,
                                             float* __restrict__ o,
                                             const float* __restrict__ qn)
{
    int item = blockIdx.x * 8 + (threadIdx.x >> 5);
    int lane = threadIdx.x & 31;
    int h = item & 15;
    int r = item >> 4;
    int t = r >> 10;
    int u0 = max(0, t - 5);
    int nu = t - u0 + 1;

    const float* qp = q + (size_t)r * 1024 + h * 64;
    float q0 = qp[lane], q1 = qp[lane + 32];
    rmsrope_w(q0, q1, qn, lane, t);

    float sc[6];
    float mx = -1e30f;
#pragma unroll
    for (int i = 0; i < 6; i++) {
        if (i < nu) {
            int uu = u0 + i;
            const float* kp = kv + (size_t)uu * 2048 + h * 64;
            float d = q0 * kp[lane] + q1 * kp[lane + 32];
            for (int off = 16; off; off >>= 1) d += __shfl_xor_sync(~0u, d, off);
            sc[i] = d * 0.125f;
            mx = fmaxf(mx, sc[i]);
        }
    }
    float denom = 0.f, a0 = 0.f, a1 = 0.f;
#pragma unroll
    for (int i = 0; i < 6; i++) {
        if (i < nu) {
            float p = __expf(sc[i] - mx);
            denom += p;
            int uu = u0 + i;
            const float* vp = kv + (size_t)uu * 2048 + 1024 + h * 64;
            a0 += p * vp[lane]; a1 += p * vp[lane + 32];
        }
    }
    float inv = 1.f / denom;
    float* op = o + (size_t)r * 1024 + h * 64;
    op[lane] = a0 * inv; op[lane + 32] = a1 * inv;
}

// ---------------- conditioning: keyboard MLP (+ mouse gather in block 0) ----------------
__global__ void kb_mlp(const float* __restrict__ kb,
                       const float* __restrict__ w1, const float* __restrict__ b1,
                       const float* __restrict__ w2, const float* __restrict__ b2,
                       const float* __restrict__ mouse)
{
    int n = blockIdx.x;
    int c = threadIdx.x;  // 128
    if (n == 0) {
        for (int i = c; i < TT * 24; i += 128) {
            int t = i / 24, j2 = i % 24;
            g_gm[i] = mouse[(4 * t + (j2 >> 1)) * 2 + (j2 & 1)];
        }
    }
    __shared__ float hid[128];
    float a = b1[c];
#pragma unroll
    for (int i = 0; i < 6; i++) a += kb[n * 6 + i] * w1[i * 128 + c];
    hid[c] = a / (1.f + __expf(-a));
    __syncthreads();
    float ov = b2[c];
    for (int i = 0; i < 128; i++) ov += hid[i] * w2[i * 128 + c];
    g_kc[n * 128 + c] = ov;
}

// ---------------- conditioning: kv projection + k rms+rope fused ----------------
__global__ void kv_gemm(const float* __restrict__ wkv, const float* __restrict__ knw)
{
    int t = blockIdx.x;
    __shared__ float gk[1536];
    __shared__ float out[2048];
    for (int i = threadIdx.x; i < 1536; i += 256)
        gk[i] = g_kc[(4 * t + i / 128) * 128 + (i & 127)];
    __syncthreads();
    for (int oc = threadIdx.x; oc < 2048; oc += 256) {
        float a = 0.f;
        for (int i = 0; i < 1536; i++) a += gk[i] * wkv[(size_t)i * 2048 + oc];
        out[oc] = a;
    }
    __syncthreads();
    int warp = threadIdx.x >> 5, lane = threadIdx.x & 31;
#pragma unroll
    for (int hh = 0; hh < 2; hh++) {
        int h = warp * 2 + hh;
        float v0 = out[h * 64 + lane], v1 = out[h * 64 + lane + 32];
        rmsrope_w(v0, v1, knw, lane, t);
        out[h * 64 + lane] = v0; out[h * 64 + lane + 32] = v1;
    }
    __syncthreads();
    for (int i = threadIdx.x; i < 2048; i += 256)
        g_kv[t * 2048 + i] = out[i];
}

// ---------------- host ----------------
extern "C" void kernel_launch(void* const* d_in, const int* in_sizes, int n_in,
                              void* d_out, int out_size)
{
    int wb = (in_sizes[3] == 1) ? 6 : 3;
    const float* x       = (const float*)d_in[0];
    const float* mouse   = (const float*)d_in[1];
    const float* kb      = (const float*)d_in[2];
    const float* kb_w1   = (const float*)d_in[wb + 0];
    const float* kb_b1   = (const float*)d_in[wb + 1];
    const float* kb_w2   = (const float*)d_in[wb + 2];
    const float* kb_b2   = (const float*)d_in[wb + 3];
    const float* mm_w1   = (const float*)d_in[wb + 4];
    const float* mm_b1   = (const float*)d_in[wb + 5];
    const float* mm_w2   = (const float*)d_in[wb + 6];
    const float* mm_b2   = (const float*)d_in[wb + 7];
    const float* ln_g    = (const float*)d_in[wb + 8];
    const float* ln_b    = (const float*)d_in[wb + 9];
    const float* qkv_w   = (const float*)d_in[wb + 10];
    const float* qn_img  = (const float*)d_in[wb + 11];
    const float* kn_img  = (const float*)d_in[wb + 12];
    const float* qn_key  = (const float*)d_in[wb + 13];
    const float* kn_key  = (const float*)d_in[wb + 14];
    const float* proj_mouse_w = (const float*)d_in[wb + 15];
    const float* wq_key  = (const float*)d_in[wb + 16];
    const float* wkv_key = (const float*)d_in[wb + 17];
    const float* proj_key_w   = (const float*)d_in[wb + 18];

    float *p_kv, *p_h1, *p_h2, *p_qkv, *p_o, *p_hidden, *p_qh, *p_mext;
    float *w1t, *w2t, *w3t, *w4t, *w5t, *w6t;
    cudaGetSymbolAddress((void**)&p_kv, g_kv);
    cudaGetSymbolAddress((void**)&p_h1, g_h1);
    cudaGetSymbolAddress((void**)&p_h2, g_h2);
    cudaGetSymbolAddress((void**)&p_qkv, g_qkv);
    cudaGetSymbolAddress((void**)&p_o, g_o);
    cudaGetSymbolAddress((void**)&p_hidden, g_hidden);
    cudaGetSymbolAddress((void**)&p_qh, g_qh);
    cudaGetSymbolAddress((void**)&p_mext, g_mext);
    cudaGetSymbolAddress((void**)&w1t, g_wt1);
    cudaGetSymbolAddress((void**)&w2t, g_wt2);
    cudaGetSymbolAddress((void**)&w3t, g_wt3);
    cudaGetSymbolAddress((void**)&w4t, g_wt4);
    cudaGetSymbolAddress((void**)&w5t, g_wt5);
    cudaGetSymbolAddress((void**)&w6t, g_wt6);

    cudaFuncSetAttribute(tgemm, cudaFuncAttributeMaxDynamicSharedMemorySize, GEMM_SMEM);

    // one fused transpose launch for all six weights
    TPack tp;
    tp.src[0] = mm_w1;        tp.dst[0] = w1t; tp.R[0] = 1560; tp.C[0] = 1024;
    tp.src[1] = mm_w2;        tp.dst[1] = w2t; tp.R[1] = 1024; tp.C[1] = 1024;
    tp.src[2] = qkv_w;        tp.dst[2] = w3t; tp.R[2] = 1024; tp.C[2] = 3072;
    tp.src[3] = proj_mouse_w; tp.dst[3] = w4t; tp.R[3] = 1024; tp.C[3] = 1536;
    tp.src[4] = wq_key;       tp.dst[4] = w5t; tp.R[4] = 1536; tp.C[4] = 1024;
    tp.src[5] = proj_key_w;   tp.dst[5] = w6t; tp.R[5] = 1024; tp.C[5] = 1536;
    transpose_all<<<dim3(96, 49, 6), dim3(32, 8)>>>(tp);

    // conditioning path
    kb_mlp<<<NF, 128>>>(kb, kb_w1, kb_b1, kb_w2, kb_b2, mouse);
    mext_kernel<<<TT, 256>>>(w1t);
    kv_gemm<<<TT, 256>>>(wkv_key, kn_key);

    const int MB = LTOK / 128;  // 192

    // GEMM1: x @ mm_w1[:1536] + b1 + mext[frame], gelu  (K=1536; mouse tail via extra)
    tgemm<<<dim3(HID / 256, MB), 256, GEMM_SMEM>>>(x, CDIM, w1t, 1560, p_h1,
                                                   mm_b1, nullptr, p_mext, HID, 1536, 1);
    // GEMM2: h1 @ mm_w2 + b2
    tgemm<<<dim3(HID / 256, MB), 256, GEMM_SMEM>>>(p_h1, HID, w2t, HID, p_h2,
                                                   mm_b2, nullptr, nullptr, HID, HID, 0);
    ln_kernel<<<LTOK, 256>>>(p_h2, ln_g, ln_b);

    // GEMM3: qkv
    tgemm<<<dim3(3 * HID / 256, MB), 256, GEMM_SMEM>>>(p_h2, HID, w3t, HID, p_qkv,
                                                       nullptr, nullptr, nullptr, 3 * HID, HID, 0);
    attn1<<<dim3(SSP, NHEAD), 256>>>(p_qkv, p_o, qn_img, kn_img);

    // GEMM4: hidden = x + o @ proj_mouse_w
    tgemm<<<dim3(CDIM / 256, MB), 256, GEMM_SMEM>>>(p_o, HID, w4t, HID, p_hidden,
                                                    nullptr, x, nullptr, CDIM, HID, 2);
    // GEMM5: qh = hidden @ wq_key
    tgemm<<<dim3(HID / 256, MB), 256, GEMM_SMEM>>>(p_hidden, CDIM, w5t, CDIM, p_qh,
                                                   nullptr, nullptr, nullptr, HID, CDIM, 0);
    attn2<<<(LTOK * NHEAD) / 8, 256>>>(p_qh, p_kv, p_o, qn_key);

    // GEMM6: out = hidden + o2 @ proj_key_w
    tgemm<<<dim3(CDIM / 256, MB), 256, GEMM_SMEM>>>(p_o, HID, w6t, HID, (float*)d_out,
                                                    nullptr, p_hidden, nullptr, CDIM, HID, 2);
}

// round 7
// speedup vs baseline: 3.5861x; 1.0751x over previous
#include <cuda_runtime.h>
#include <math.h>
#include <stdint.h>

#define LTOK 24576
#define SSP  1024
#define TT   24
#define CDIM 1536
#define HID  1024
#define NHEAD 16
#define NF   104

// ---------------- scratch (device globals; allocation-free rule) ----------------
__device__ __align__(128) float g_kc[NF * 128];
__device__ __align__(128) float g_gm[TT * 24];
__device__ __align__(128) float g_mext[TT * 1024];
__device__ __align__(128) float g_kv[TT * 2048];
__device__ __align__(128) float g_h1[(size_t)LTOK * HID];
__device__ __align__(128) float g_h2[(size_t)LTOK * HID];
__device__ __align__(128) float g_qkv[(size_t)LTOK * 3 * HID];
__device__ __align__(128) float g_o[(size_t)LTOK * HID];
__device__ __align__(128) float g_hidden[(size_t)LTOK * CDIM];
__device__ __align__(128) float g_qh[(size_t)LTOK * HID];
// transposed weights [N][K]
__device__ __align__(128) float g_wt1[1024 * 1560];
__device__ __align__(128) float g_wt2[1024 * 1024];
__device__ __align__(128) float g_wt3[3072 * 1024];
__device__ __align__(128) float g_wt4[1536 * 1024];
__device__ __align__(128) float g_wt5[1024 * 1536];
__device__ __align__(128) float g_wt6[1536 * 1024];

// ---------------- fused weight transpose (all 6 in one launch) ----------------
struct TPack {
    const float* src[6];
    float* dst[6];
    int R[6];
    int C[6];
};

__global__ void transpose_all(TPack p)
{
    __shared__ float t[32][33];
    int z = blockIdx.z;
    int R = p.R[z], C = p.C[z];
    int c0 = blockIdx.x * 32, r0 = blockIdx.y * 32;
    if (c0 >= C || r0 >= R) return;
    const float* in = p.src[z];
    float* out = p.dst[z];
    int x = threadIdx.x, y = threadIdx.y;  // 32 x 8
#pragma unroll
    for (int i = 0; i < 32; i += 8) {
        int r = r0 + y + i, c = c0 + x;
        t[y + i][x] = (r < R && c < C) ? in[(size_t)r * C + c] : 0.f;
    }
    __syncthreads();
#pragma unroll
    for (int i = 0; i < 32; i += 8) {
        int r = c0 + y + i, c = r0 + x;  // out is [C][R]
        if (r < C && c < R) out[(size_t)r * R + c] = t[x][y + i];
    }
}

// ---------------- mouse rank-24 contribution: mext[t][col] = sum_k gm[t][k] * w1t[col][1536+k]
__global__ void mext_kernel(const float* __restrict__ w1t)
{
    int t = blockIdx.x;
    __shared__ float gm[24];
    if (threadIdx.x < 24) gm[threadIdx.x] = g_gm[t * 24 + threadIdx.x];
    __syncthreads();
    for (int col = threadIdx.x; col < 1024; col += 256) {
        const float* wp = w1t + (size_t)col * 1560 + 1536;
        float s = 0.f;
#pragma unroll
        for (int k = 0; k < 24; k++) s += gm[k] * wp[k];
        g_mext[t * 1024 + col] = s;
    }
}

// ---------------- TF32 tensor-core GEMM: 128x256 tile, cp.async 4-stage + ldmatrix ----------------
#define STAGES 4
#define STBYTES 49152            // per stage: A 16KB + B 32KB
#define GEMM_SMEM (STAGES * STBYTES)

__device__ __forceinline__ void mma8(float* c, uint32_t a0, uint32_t a1, uint32_t a2,
                                     uint32_t a3, uint32_t b0, uint32_t b1) {
    asm volatile(
        "mma.sync.aligned.m16n8k8.row.col.f32.tf32.tf32.f32 "
        "{%0,%1,%2,%3}, {%4,%5,%6,%7}, {%8,%9}, {%0,%1,%2,%3};"
        : "+f"(c[0]), "+f"(c[1]), "+f"(c[2]), "+f"(c[3])
        : "r"(a0), "r"(a1), "r"(a2), "r"(a3), "r"(b0), "r"(b1));
}

#define LDSM4(P, ADDR)                                                   \
    asm volatile("ldmatrix.sync.aligned.m8n8.x4.b16 {%0,%1,%2,%3}, [%4];" \
                 : "=r"((P)[0]), "=r"((P)[1]), "=r"((P)[2]), "=r"((P)[3]) \
                 : "r"(ADDR))

__device__ __forceinline__ void cpa16(uint32_t dst, const float* src) {
    asm volatile("cp.async.cg.shared.global [%0], [%1], 16;\n"
                 :: "r"(dst), "l"(src));
}

__device__ __forceinline__ float gelu_fast(float v) {
    float u2 = 1.5957691216057308f * (v + 0.044715f * v * v * v);
    return __fdividef(v, 1.f + __expf(-u2));
}

// K % 32 == 0, N % 256 == 0, M % 128 == 0 — no guards anywhere.
// epi: 0 = bias(optional), 1 = bias+gelu (+extra per-frame row add), 2 = residual add
__global__ void __launch_bounds__(256, 1) tgemm(
    const float* __restrict__ A, int lda,
    const float* __restrict__ Bt, int ldb,
    float* __restrict__ Cout,
    const float* __restrict__ bias,
    const float* __restrict__ addsrc,
    const float* __restrict__ extra,
    int N, int K, int epi)
{
    extern __shared__ float smem[];
    const int tid = threadIdx.x, lane = tid & 31, warp = tid >> 5;
    const int wm = warp & 1, wn = warp >> 1;            // 2x4 warps -> 64x64 tiles
    const int rowBase = blockIdx.y * 128, colBase = blockIdx.x * 256;
    const int nk = K >> 5;
    uint32_t sbase = (uint32_t)__cvta_generic_to_shared(smem);

    // loader: thread handles k-unit u (4 floats) of A rows arow+32i (i<4) and B rows arow+32j (j<8)
    const int arow = tid >> 3;
    const int u = tid & 7;
    const uint32_t swz = (uint32_t)(arow * 128 + ((u ^ (arow & 7)) << 4));
    const uint32_t dstA0 = sbase + swz;
    const uint32_t dstB0 = sbase + 16384 + swz;

    const float* pa[4];
    const float* pb[8];
#pragma unroll
    for (int i = 0; i < 4; i++)
        pa[i] = A + (size_t)(rowBase + arow + 32 * i) * lda + u * 4;
#pragma unroll
    for (int j = 0; j < 8; j++)
        pb[j] = Bt + (size_t)(colBase + arow + 32 * j) * ldb + u * 4;

    // compute-side constants
    const int mtx = lane >> 3, rl = lane & 7;
    const int rA = wm * 64 + ((mtx >> 1) << 3) + rl;
    const int rB = wn * 64 + ((mtx >> 1) << 3) + rl;
    const int usel = mtx & 1;
    const int axor = rA & 7, bxor = rB & 7;
    const uint32_t aoff = (uint32_t)(rA * 128);
    const uint32_t boff = (uint32_t)(16384 + rB * 128);

    float acc[4][8][4];
#pragma unroll
    for (int a = 0; a < 4; a++)
#pragma unroll
        for (int b = 0; b < 8; b++)
#pragma unroll
            for (int c = 0; c < 4; c++) acc[a][b][c] = 0.f;

#define ISSUE(STG)                                                            \
    {                                                                         \
        uint32_t sA = dstA0 + (STG) * STBYTES;                                \
        uint32_t sB = dstB0 + (STG) * STBYTES;                                \
        _Pragma("unroll")                                                     \
        for (int i = 0; i < 4; i++) { cpa16(sA + i * 4096, pa[i]); pa[i] += 32; } \
        _Pragma("unroll")                                                     \
        for (int j = 0; j < 8; j++) { cpa16(sB + j * 4096, pb[j]); pb[j] += 32; } \
        asm volatile("cp.async.commit_group;\n");                             \
    }

#define COMPUTE(STG)                                                          \
    {                                                                         \
        uint32_t sb = sbase + (STG) * STBYTES;                                \
        _Pragma("unroll")                                                     \
        for (int kk = 0; kk < 4; kk++) {                                      \
            uint32_t ua = (uint32_t)(((2 * kk + usel) ^ axor) << 4);          \
            uint32_t ub = (uint32_t)(((2 * kk + usel) ^ bxor) << 4);          \
            uint32_t afr[4][4], bfr[4][4];                                    \
            _Pragma("unroll")                                                 \
            for (int mt = 0; mt < 4; mt++)                                    \
                LDSM4(afr[mt], sb + aoff + ua + mt * 2048);                   \
            _Pragma("unroll")                                                 \
            for (int p = 0; p < 4; p++)                                       \
                LDSM4(bfr[p], sb + boff + ub + p * 2048);                     \
            _Pragma("unroll")                                                 \
            for (int mt = 0; mt < 4; mt++)                                    \
                _Pragma("unroll")                                             \
                for (int nt = 0; nt < 8; nt++)                                \
                    mma8(acc[mt][nt],                                         \
                         afr[mt][0], afr[mt][2], afr[mt][1], afr[mt][3],      \
                         bfr[nt >> 1][(nt & 1) * 2], bfr[nt >> 1][(nt & 1) * 2 + 1]); \
        }                                                                     \
    }

    ISSUE(0);
    ISSUE(1);
    ISSUE(2);
    for (int t = 0; t < nk; t++) {
        asm volatile("cp.async.wait_group %0;\n" :: "n"(STAGES - 2));
        __syncthreads();
        int pf = t + STAGES - 1;
        if (pf < nk) { ISSUE(pf & 3); }
        else { asm volatile("cp.async.commit_group;\n"); }
        COMPUTE(t & 3);
    }

    // epilogue
#pragma unroll
    for (int mt = 0; mt < 4; mt++) {
#pragma unroll
        for (int nt = 0; nt < 8; nt++) {
            int col = colBase + wn * 64 + nt * 8 + (lane & 3) * 2;
#pragma unroll
            for (int half = 0; half < 2; half++) {
                int row = rowBase + wm * 64 + mt * 16 + (lane >> 2) + half * 8;
                float v0 = acc[mt][nt][half * 2 + 0];
                float v1 = acc[mt][nt][half * 2 + 1];
                if (bias) { v0 += bias[col]; v1 += bias[col + 1]; }
                if (epi == 1) {
                    const float* ep = extra + (size_t)(row >> 10) * N + col;
                    v0 = gelu_fast(v0 + ep[0]);
                    v1 = gelu_fast(v1 + ep[1]);
                } else if (epi == 2) {
                    float2 a = *(const float2*)(addsrc + (size_t)row * N + col);
                    v0 += a.x; v1 += a.y;
                }
                float2 o; o.x = v0; o.y = v1;
                *(float2*)(Cout + (size_t)row * N + col) = o;
            }
        }
    }
#undef ISSUE
#undef COMPUTE
}

// ---------------- LayerNorm over HID=1024, in place ----------------
__global__ void __launch_bounds__(256) ln_kernel(float* __restrict__ h,
                                                 const float* __restrict__ g,
                                                 const float* __restrict__ b)
{
    __shared__ float row[1024];
    __shared__ float red[8];
    __shared__ float meanv, rstdv;
    int r = blockIdx.x;
    float* hp = h + (size_t)r * 1024;
    int tid = threadIdx.x;
    float s = 0.f;
    for (int i = tid; i < 1024; i += 256) { float v = hp[i]; row[i] = v; s += v; }
    for (int o = 16; o; o >>= 1) s += __shfl_xor_sync(~0u, s, o);
    if ((tid & 31) == 0) red[tid >> 5] = s;
    __syncthreads();
    if (tid == 0) { float t = 0; for (int i = 0; i < 8; i++) t += red[i]; meanv = t * (1.f / 1024.f); }
    __syncthreads();
    float m = meanv;
    float ss = 0.f;
    for (int i = tid; i < 1024; i += 256) { float d = row[i] - m; ss += d * d; }
    for (int o = 16; o; o >>= 1) ss += __shfl_xor_sync(~0u, ss, o);
    if ((tid & 31) == 0) red[tid >> 5] = ss;
    __syncthreads();
    if (tid == 0) { float t = 0; for (int i = 0; i < 8; i++) t += red[i]; rstdv = rsqrtf(t * (1.f / 1024.f) + 1e-5f); }
    __syncthreads();
    float rs = rstdv;
    for (int i = tid; i < 1024; i += 256) hp[i] = (row[i] - m) * rs * g[i] + b[i];
}

// ---------------- fused RMSNorm + RoPE (register-level, per warp row) ----------------
__device__ __forceinline__ void rmsrope_w(float& v0, float& v1,
                                          const float* __restrict__ w, int lane, int t)
{
    float ss = v0 * v0 + v1 * v1;
    for (int o = 16; o; o >>= 1) ss += __shfl_xor_sync(~0u, ss, o);
    float rs = rsqrtf(ss * (1.f / 64.f) + 1e-6f);
    v0 = v0 * rs * w[lane];
    v1 = v1 * rs * w[lane + 32];
    float other = __shfl_xor_sync(~0u, v0, 1);
    if (lane < 8) {
        float inv = exp2f(-2.f * (float)(lane >> 1));
        float ang = (float)t * inv;
        float c, s;
        sincosf(ang, &s, &c);
        float rot = (lane & 1) ? other : -other;
        v0 = v0 * c + rot * s;
    }
}

// ---------------- attn1: smem-tiled per (s, h), fused q/k rms+rope ----------------
__global__ void __launch_bounds__(256) attn1(const float* __restrict__ qkv,
                                             float* __restrict__ o,
                                             const float* __restrict__ qn,
                                             const float* __restrict__ kn)
{
    __shared__ float ks[24][64];
    __shared__ float vs[24][64];
    int s = blockIdx.x, h = blockIdx.y;
    int warp = threadIdx.x >> 5, lane = threadIdx.x & 31;

#pragma unroll
    for (int j = 0; j < 3; j++) {
        int t = warp * 3 + j;
        const float* base = qkv + (size_t)(t * 1024 + s) * 3072 + h * 64;
        float k0 = base[1024 + lane], k1 = base[1024 + lane + 32];
        rmsrope_w(k0, k1, kn, lane, t);
        ks[t][lane] = k0; ks[t][lane + 32] = k1;
        vs[t][lane] = base[2048 + lane];
        vs[t][lane + 32] = base[2048 + lane + 32];
    }
    __syncthreads();

#pragma unroll
    for (int j = 0; j < 3; j++) {
        int t = warp * 3 + j;
        const float* qp = qkv + (size_t)(t * 1024 + s) * 3072 + h * 64;
        float q0 = qp[lane], q1 = qp[lane + 32];
        rmsrope_w(q0, q1, qn, lane, t);
        int u0 = max(0, t - 5);
        int nu = t - u0 + 1;
        float sc[6];
        float mx = -1e30f;
#pragma unroll
        for (int i = 0; i < 6; i++) {
            if (i < nu) {
                int uu = u0 + i;
                float d = q0 * ks[uu][lane] + q1 * ks[uu][lane + 32];
                for (int off = 16; off; off >>= 1) d += __shfl_xor_sync(~0u, d, off);
                sc[i] = d * 0.125f;
                mx = fmaxf(mx, sc[i]);
            }
        }
        float denom = 0.f, a0 = 0.f, a1 = 0.f;
#pragma unroll
        for (int i = 0; i < 6; i++) {
            if (i < nu) {
                float p = __expf(sc[i] - mx);
                denom += p;
                int uu = u0 + i;
                a0 += p * vs[uu][lane]; a1 += p * vs[uu][lane + 32];
            }
        }
        float inv = 1.f / denom;
        float* op = o + (size_t)(t * 1024 + s) * 1024 + h * 64;
        op[lane] = a0 * inv; op[lane + 32] = a1 * inv;
    }
}

// ---------------- attn2: keyboard cross-attn, fused q rms+rope ----------------
__global__ void __launch_bounds__(256) attn2(const float* __restrict__ q,
                                             const float* __restrict__ kv,
                                             float* __restrict__ o,
                                             const float* __restrict__ qn)
{
    int item = blockIdx.x * 8 + (threadIdx.x >> 5);
    int lane = threadIdx.x & 31;
    int h = item & 15;
    int r = item >> 4;
    int t = r >> 10;
    int u0 = max(0, t - 5);
    int nu = t - u0 + 1;

    const float* qp = q + (size_t)r * 1024 + h * 64;
    float q0 = qp[lane], q1 = qp[lane + 32];
    rmsrope_w(q0, q1, qn, lane, t);

    float sc[6];
    float mx = -1e30f;
#pragma unroll
    for (int i = 0; i < 6; i++) {
        if (i < nu) {
            int uu = u0 + i;
            const float* kp = kv + (size_t)uu * 2048 + h * 64;
            float d = q0 * kp[lane] + q1 * kp[lane + 32];
            for (int off = 16; off; off >>= 1) d += __shfl_xor_sync(~0u, d, off);
            sc[i] = d * 0.125f;
            mx = fmaxf(mx, sc[i]);
        }
    }
    float denom = 0.f, a0 = 0.f, a1 = 0.f;
#pragma unroll
    for (int i = 0; i < 6; i++) {
        if (i < nu) {
            float p = __expf(sc[i] - mx);
            denom += p;
            int uu = u0 + i;
            const float* vp = kv + (size_t)uu * 2048 + 1024 + h * 64;
            a0 += p * vp[lane]; a1 += p * vp[lane + 32];
        }
    }
    float inv = 1.f / denom;
    float* op = o + (size_t)r * 1024 + h * 64;
    op[lane] = a0 * inv; op[lane + 32] = a1 * inv;
}

// ---------------- conditioning: keyboard MLP (+ mouse gather in block 0) ----------------
__global__ void kb_mlp(const float* __restrict__ kb,
                       const float* __restrict__ w1, const float* __restrict__ b1,
                       const float* __restrict__ w2, const float* __restrict__ b2,
                       const float* __restrict__ mouse)
{
    int n = blockIdx.x;
    int c = threadIdx.x;  // 128
    if (n == 0) {
        for (int i = c; i < TT * 24; i += 128) {
            int t = i / 24, j2 = i % 24;
            g_gm[i] = mouse[(4 * t + (j2 >> 1)) * 2 + (j2 & 1)];
        }
    }
    __shared__ float hid[128];
    float a = b1[c];
#pragma unroll
    for (int i = 0; i < 6; i++) a += kb[n * 6 + i] * w1[i * 128 + c];
    hid[c] = a / (1.f + __expf(-a));
    __syncthreads();
    float ov = b2[c];
    for (int i = 0; i < 128; i++) ov += hid[i] * w2[i * 128 + c];
    g_kc[n * 128 + c] = ov;
}

// ---------------- conditioning: kv projection + k rms+rope, parallel version ----------------
// grid (TT, 8): block (t, cb) computes out cols [cb*256, cb*256+256)
__global__ void __launch_bounds__(256) kv_gemm(const float* __restrict__ wkv,
                                               const float* __restrict__ knw)
{
    int t = blockIdx.x, cb = blockIdx.y;
    __shared__ float gk[1536];
    __shared__ float out[256];
    for (int i = threadIdx.x; i < 1536; i += 256)
        gk[i] = g_kc[(4 * t + (i >> 7)) * 128 + (i & 127)];
    __syncthreads();

    int oc = cb * 256 + threadIdx.x;
    const float* wp = wkv + oc;
    float a0 = 0.f, a1 = 0.f, a2 = 0.f, a3 = 0.f;
#pragma unroll 4
    for (int i = 0; i < 1536; i += 4) {
        a0 += gk[i + 0] * wp[(size_t)(i + 0) * 2048];
        a1 += gk[i + 1] * wp[(size_t)(i + 1) * 2048];
        a2 += gk[i + 2] * wp[(size_t)(i + 2) * 2048];
        a3 += gk[i + 3] * wp[(size_t)(i + 3) * 2048];
    }
    out[threadIdx.x] = (a0 + a1) + (a2 + a3);
    __syncthreads();

    if (cb < 4) {
        // k half: this block owns 4 complete heads (head = cb*4 + hh)
        int warp = threadIdx.x >> 5, lane = threadIdx.x & 31;
        if (warp < 4) {
            int hh = warp;
            float v0 = out[hh * 64 + lane], v1 = out[hh * 64 + lane + 32];
            rmsrope_w(v0, v1, knw, lane, t);
            out[hh * 64 + lane] = v0; out[hh * 64 + lane + 32] = v1;
        }
        __syncthreads();
    }
    g_kv[t * 2048 + oc] = out[threadIdx.x];
}

// ---------------- host ----------------
extern "C" void kernel_launch(void* const* d_in, const int* in_sizes, int n_in,
                              void* d_out, int out_size)
{
    int wb = (in_sizes[3] == 1) ? 6 : 3;
    const float* x       = (const float*)d_in[0];
    const float* mouse   = (const float*)d_in[1];
    const float* kb      = (const float*)d_in[2];
    const float* kb_w1   = (const float*)d_in[wb + 0];
    const float* kb_b1   = (const float*)d_in[wb + 1];
    const float* kb_w2   = (const float*)d_in[wb + 2];
    const float* kb_b2   = (const float*)d_in[wb + 3];
    const float* mm_w1   = (const float*)d_in[wb + 4];
    const float* mm_b1   = (const float*)d_in[wb + 5];
    const float* mm_w2   = (const float*)d_in[wb + 6];
    const float* mm_b2   = (const float*)d_in[wb + 7];
    const float* ln_g    = (const float*)d_in[wb + 8];
    const float* ln_b    = (const float*)d_in[wb + 9];
    const float* qkv_w   = (const float*)d_in[wb + 10];
    const float* qn_img  = (const float*)d_in[wb + 11];
    const float* kn_img  = (const float*)d_in[wb + 12];
    const float* qn_key  = (const float*)d_in[wb + 13];
    const float* kn_key  = (const float*)d_in[wb + 14];
    const float* proj_mouse_w = (const float*)d_in[wb + 15];
    const float* wq_key  = (const float*)d_in[wb + 16];
    const float* wkv_key = (const float*)d_in[wb + 17];
    const float* proj_key_w   = (const float*)d_in[wb + 18];

    float *p_kv, *p_h1, *p_h2, *p_qkv, *p_o, *p_hidden, *p_qh, *p_mext;
    float *w1t, *w2t, *w3t, *w4t, *w5t, *w6t;
    cudaGetSymbolAddress((void**)&p_kv, g_kv);
    cudaGetSymbolAddress((void**)&p_h1, g_h1);
    cudaGetSymbolAddress((void**)&p_h2, g_h2);
    cudaGetSymbolAddress((void**)&p_qkv, g_qkv);
    cudaGetSymbolAddress((void**)&p_o, g_o);
    cudaGetSymbolAddress((void**)&p_hidden, g_hidden);
    cudaGetSymbolAddress((void**)&p_qh, g_qh);
    cudaGetSymbolAddress((void**)&p_mext, g_mext);
    cudaGetSymbolAddress((void**)&w1t, g_wt1);
    cudaGetSymbolAddress((void**)&w2t, g_wt2);
    cudaGetSymbolAddress((void**)&w3t, g_wt3);
    cudaGetSymbolAddress((void**)&w4t, g_wt4);
    cudaGetSymbolAddress((void**)&w5t, g_wt5);
    cudaGetSymbolAddress((void**)&w6t, g_wt6);

    cudaFuncSetAttribute(tgemm, cudaFuncAttributeMaxDynamicSharedMemorySize, GEMM_SMEM);

    // one fused transpose launch for all six weights
    TPack tp;
    tp.src[0] = mm_w1;        tp.dst[0] = w1t; tp.R[0] = 1560; tp.C[0] = 1024;
    tp.src[1] = mm_w2;        tp.dst[1] = w2t; tp.R[1] = 1024; tp.C[1] = 1024;
    tp.src[2] = qkv_w;        tp.dst[2] = w3t; tp.R[2] = 1024; tp.C[2] = 3072;
    tp.src[3] = proj_mouse_w; tp.dst[3] = w4t; tp.R[3] = 1024; tp.C[3] = 1536;
    tp.src[4] = wq_key;       tp.dst[4] = w5t; tp.R[4] = 1536; tp.C[4] = 1024;
    tp.src[5] = proj_key_w;   tp.dst[5] = w6t; tp.R[5] = 1024; tp.C[5] = 1536;
    transpose_all<<<dim3(96, 49, 6), dim3(32, 8)>>>(tp);

    // conditioning path
    kb_mlp<<<NF, 128>>>(kb, kb_w1, kb_b1, kb_w2, kb_b2, mouse);
    mext_kernel<<<TT, 256>>>(w1t);
    kv_gemm<<<dim3(TT, 8), 256>>>(wkv_key, kn_key);

    const int MB = LTOK / 128;  // 192

    // GEMM1: x @ mm_w1[:1536] + b1 + mext[frame], gelu  (K=1536; mouse tail via extra)
    tgemm<<<dim3(HID / 256, MB), 256, GEMM_SMEM>>>(x, CDIM, w1t, 1560, p_h1,
                                                   mm_b1, nullptr, p_mext, HID, 1536, 1);
    // GEMM2: h1 @ mm_w2 + b2
    tgemm<<<dim3(HID / 256, MB), 256, GEMM_SMEM>>>(p_h1, HID, w2t, HID, p_h2,
                                                   mm_b2, nullptr, nullptr, HID, HID, 0);
    ln_kernel<<<LTOK, 256>>>(p_h2, ln_g, ln_b);

    // GEMM3: qkv
    tgemm<<<dim3(3 * HID / 256, MB), 256, GEMM_SMEM>>>(p_h2, HID, w3t, HID, p_qkv,
                                                       nullptr, nullptr, nullptr, 3 * HID, HID, 0);
    attn1<<<dim3(SSP, NHEAD), 256>>>(p_qkv, p_o, qn_img, kn_img);

    // GEMM4: hidden = x + o @ proj_mouse_w
    tgemm<<<dim3(CDIM / 256, MB), 256, GEMM_SMEM>>>(p_o, HID, w4t, HID, p_hidden,
                                                    nullptr, x, nullptr, CDIM, HID, 2);
    // GEMM5: qh = hidden @ wq_key
    tgemm<<<dim3(HID / 256, MB), 256, GEMM_SMEM>>>(p_hidden, CDIM, w5t, CDIM, p_qh,
                                                   nullptr, nullptr, nullptr, HID, CDIM, 0);
    attn2<<<(LTOK * NHEAD) / 8, 256>>>(p_qh, p_kv, p_o, qn_key);

    // GEMM6: out = hidden + o2 @ proj_key_w
    tgemm<<<dim3(CDIM / 256, MB), 256, GEMM_SMEM>>>(p_o, HID, w6t, HID, (float*)d_out,
                                                    nullptr, p_hidden, nullptr, CDIM, HID, 2);
}

// round 9
// speedup vs baseline: 4.0231x; 1.1218x over previous
#include <cuda_runtime.h>
#include <math.h>
#include <stdint.h>

#define LTOK 24576
#define SSP  1024
#define TT   24
#define CDIM 1536
#define HID  1024
#define NHEAD 16
#define NF   104

// ---------------- scratch (device globals; allocation-free rule) ----------------
__device__ __align__(128) float g_kc[NF * 128];
__device__ __align__(128) float g_gm[TT * 24];
__device__ __align__(128) float g_mext[TT * 1024];
__device__ __align__(128) float g_gk24[128 * 1536];
__device__ __align__(128) float g_kvpad[128 * 2048];
__device__ __align__(128) float g_h1[(size_t)LTOK * HID];
__device__ __align__(128) float g_h2[(size_t)LTOK * HID];
__device__ __align__(128) float g_qkv[(size_t)LTOK * 3 * HID];
__device__ __align__(128) float g_o[(size_t)LTOK * HID];
__device__ __align__(128) float g_hidden[(size_t)LTOK * CDIM];
__device__ __align__(128) float g_qh[(size_t)LTOK * HID];
// transposed weights [N][K]
__device__ __align__(128) float g_wt1[1024 * 1560];
__device__ __align__(128) float g_wt2[1024 * 1024];
__device__ __align__(128) float g_wt3[3072 * 1024];
__device__ __align__(128) float g_wt4[1536 * 1024];
__device__ __align__(128) float g_wt5[1024 * 1536];
__device__ __align__(128) float g_wt6[1536 * 1024];
__device__ __align__(128) float g_wt7[2048 * 1536];

// ---------------- fused weight transpose (all 7 in one launch) ----------------
struct TPack {
    const float* src[7];
    float* dst[7];
    int R[7];
    int C[7];
};

__global__ void transpose_all(TPack p)
{
    __shared__ float t[32][33];
    int z = blockIdx.z;
    int R = p.R[z], C = p.C[z];
    int c0 = blockIdx.x * 32, r0 = blockIdx.y * 32;
    if (c0 >= C || r0 >= R) return;
    const float* in = p.src[z];
    float* out = p.dst[z];
    int x = threadIdx.x, y = threadIdx.y;  // 32 x 8
#pragma unroll
    for (int i = 0; i < 32; i += 8) {
        int r = r0 + y + i, c = c0 + x;
        t[y + i][x] = (r < R && c < C) ? in[(size_t)r * C + c] : 0.f;
    }
    __syncthreads();
#pragma unroll
    for (int i = 0; i < 32; i += 8) {
        int r = c0 + y + i, c = r0 + x;  // out is [C][R]
        if (r < C && c < R) out[(size_t)r * R + c] = t[x][y + i];
    }
}

// ---------------- mouse rank-24 contribution: mext[t][col] = sum_k gm[t][k] * w1t[col][1536+k]
__global__ void mext_kernel(const float* __restrict__ w1t)
{
    int t = blockIdx.x;
    __shared__ float gm[24];
    if (threadIdx.x < 24) gm[threadIdx.x] = g_gm[t * 24 + threadIdx.x];
    __syncthreads();
    for (int col = threadIdx.x; col < 1024; col += 256) {
        const float* wp = w1t + (size_t)col * 1560 + 1536;
        float s = 0.f;
#pragma unroll
        for (int k = 0; k < 24; k++) s += gm[k] * wp[k];
        g_mext[t * 1024 + col] = s;
    }
}

// ---------------- build zero-padded gk24 [128][1536] (rows 0..23 real) ----------------
__global__ void gk_build()
{
    int row = blockIdx.x;  // 0..127
    for (int i = threadIdx.x; i < 1536; i += 256)
        g_gk24[row * 1536 + i] = (row < 24)
            ? g_kc[(4 * row + (i >> 7)) * 128 + (i & 127)] : 0.f;
}

// ---------------- TF32 tensor-core GEMM: 128x128 tile, cp.async 3-stage, 2 CTA/SM ----------------
#define STAGES 3
#define STBYTES 32768            // per stage: A 16KB + B 16KB
#define GEMM_SMEM (STAGES * STBYTES)

__device__ __forceinline__ void mma8(float* c, uint32_t a0, uint32_t a1, uint32_t a2,
                                     uint32_t a3, uint32_t b0, uint32_t b1) {
    asm volatile(
        "mma.sync.aligned.m16n8k8.row.col.f32.tf32.tf32.f32 "
        "{%0,%1,%2,%3}, {%4,%5,%6,%7}, {%8,%9}, {%0,%1,%2,%3};"
        : "+f"(c[0]), "+f"(c[1]), "+f"(c[2]), "+f"(c[3])
        : "r"(a0), "r"(a1), "r"(a2), "r"(a3), "r"(b0), "r"(b1));
}

#define LDSM4(P, ADDR)                                                   \
    asm volatile("ldmatrix.sync.aligned.m8n8.x4.b16 {%0,%1,%2,%3}, [%4];" \
                 : "=r"((P)[0]), "=r"((P)[1]), "=r"((P)[2]), "=r"((P)[3]) \
                 : "r"(ADDR))

__device__ __forceinline__ void cpa16(uint32_t dst, const float* src) {
    asm volatile("cp.async.cg.shared.global [%0], [%1], 16;\n"
                 :: "r"(dst), "l"(src));
}

__device__ __forceinline__ float gelu_fast(float v) {
    float u2 = 1.5957691216057308f * (v + 0.044715f * v * v * v);
    return __fdividef(v, 1.f + __expf(-u2));
}

// K % 32 == 0, N % 128 == 0, M % 128 == 0 — no guards anywhere.
// epi: 0 = bias(optional), 1 = bias+gelu (+extra per-frame row add), 2 = residual add
__global__ void __launch_bounds__(256, 2) tgemm(
    const float* __restrict__ A, int lda,
    const float* __restrict__ Bt, int ldb,
    float* __restrict__ Cout,
    const float* __restrict__ bias,
    const float* __restrict__ addsrc,
    const float* __restrict__ extra,
    int N, int K, int epi)
{
    extern __shared__ float smem[];
    const int tid = threadIdx.x, lane = tid & 31, warp = tid >> 5;
    const int wm = warp & 1, wn = warp >> 1;            // 2x4 warps -> 64x32 tiles
    const int rowBase = blockIdx.y * 128, colBase = blockIdx.x * 128;
    const int nk = K >> 5;
    uint32_t sbase = (uint32_t)__cvta_generic_to_shared(smem);

    // loader: thread handles k-unit u (4 floats) of A rows arow+32i (i<4) and B rows arow+32j (j<4)
    const int arow = tid >> 3;
    const int u = tid & 7;
    const uint32_t swz = (uint32_t)(arow * 128 + ((u ^ (arow & 7)) << 4));
    const uint32_t dstA0 = sbase + swz;
    const uint32_t dstB0 = sbase + 16384 + swz;

    const float* pa[4];
    const float* pb[4];
#pragma unroll
    for (int i = 0; i < 4; i++)
        pa[i] = A + (size_t)(rowBase + arow + 32 * i) * lda + u * 4;
#pragma unroll
    for (int j = 0; j < 4; j++)
        pb[j] = Bt + (size_t)(colBase + arow + 32 * j) * ldb + u * 4;

    // compute-side constants
    const int mtx = lane >> 3, rl = lane & 7;
    const int rA = wm * 64 + ((mtx >> 1) << 3) + rl;
    const int rB = wn * 32 + ((mtx >> 1) << 3) + rl;
    const int usel = mtx & 1;
    const int axor = rA & 7, bxor = rB & 7;
    const uint32_t aoff = (uint32_t)(rA * 128);
    const uint32_t boff = (uint32_t)(16384 + rB * 128);

    float acc[4][4][4];
#pragma unroll
    for (int a = 0; a < 4; a++)
#pragma unroll
        for (int b = 0; b < 4; b++)
#pragma unroll
            for (int c = 0; c < 4; c++) acc[a][b][c] = 0.f;

#define ISSUE(STG)                                                            \
    {                                                                         \
        uint32_t sA = dstA0 + (STG) * STBYTES;                                \
        uint32_t sB = dstB0 + (STG) * STBYTES;                                \
        _Pragma("unroll")                                                     \
        for (int i = 0; i < 4; i++) { cpa16(sA + i * 4096, pa[i]); pa[i] += 32; } \
        _Pragma("unroll")                                                     \
        for (int j = 0; j < 4; j++) { cpa16(sB + j * 4096, pb[j]); pb[j] += 32; } \
        asm volatile("cp.async.commit_group;\n");                             \
    }

#define COMPUTE(STG)                                                          \
    {                                                                         \
        uint32_t sb = sbase + (STG) * STBYTES;                                \
        _Pragma("unroll")                                                     \
        for (int kk = 0; kk < 4; kk++) {                                      \
            uint32_t ua = (uint32_t)(((2 * kk + usel) ^ axor) << 4);          \
            uint32_t ub = (uint32_t)(((2 * kk + usel) ^ bxor) << 4);          \
            uint32_t afr[4][4], bfr[2][4];                                    \
            _Pragma("unroll")                                                 \
            for (int mt = 0; mt < 4; mt++)                                    \
                LDSM4(afr[mt], sb + aoff + ua + mt * 2048);                   \
            _Pragma("unroll")                                                 \
            for (int p = 0; p < 2; p++)                                       \
                LDSM4(bfr[p], sb + boff + ub + p * 2048);                     \
            _Pragma("unroll")                                                 \
            for (int mt = 0; mt < 4; mt++)                                    \
                _Pragma("unroll")                                             \
                for (int nt = 0; nt < 4; nt++)                                \
                    mma8(acc[mt][nt],                                         \
                         afr[mt][0], afr[mt][2], afr[mt][1], afr[mt][3],      \
                         bfr[nt >> 1][(nt & 1) * 2], bfr[nt >> 1][(nt & 1) * 2 + 1]); \
        }                                                                     \
    }

    ISSUE(0);
    ISSUE(1);
    for (int t = 0; t < nk; t++) {
        asm volatile("cp.async.wait_group %0;\n" :: "n"(STAGES - 2));
        __syncthreads();
        int pf = t + STAGES - 1;
        if (pf < nk) { ISSUE(pf % STAGES); }
        else { asm volatile("cp.async.commit_group;\n"); }
        COMPUTE(t % STAGES);
    }

    // epilogue
#pragma unroll
    for (int mt = 0; mt < 4; mt++) {
#pragma unroll
        for (int nt = 0; nt < 4; nt++) {
            int col = colBase + wn * 32 + nt * 8 + (lane & 3) * 2;
#pragma unroll
            for (int half = 0; half < 2; half++) {
                int row = rowBase + wm * 64 + mt * 16 + (lane >> 2) + half * 8;
                float v0 = acc[mt][nt][half * 2 + 0];
                float v1 = acc[mt][nt][half * 2 + 1];
                if (bias) { v0 += bias[col]; v1 += bias[col + 1]; }
                if (epi == 1) {
                    const float* ep = extra + (size_t)(row >> 10) * N + col;
                    v0 = gelu_fast(v0 + ep[0]);
                    v1 = gelu_fast(v1 + ep[1]);
                } else if (epi == 2) {
                    float2 a = *(const float2*)(addsrc + (size_t)row * N + col);
                    v0 += a.x; v1 += a.y;
                }
                float2 o; o.x = v0; o.y = v1;
                *(float2*)(Cout + (size_t)row * N + col) = o;
            }
        }
    }
#undef ISSUE
#undef COMPUTE
}

// ---------------- LayerNorm over HID=1024, in place ----------------
__global__ void __launch_bounds__(256) ln_kernel(float* __restrict__ h,
                                                 const float* __restrict__ g,
                                                 const float* __restrict__ b)
{
    __shared__ float row[1024];
    __shared__ float red[8];
    __shared__ float meanv, rstdv;
    int r = blockIdx.x;
    float* hp = h + (size_t)r * 1024;
    int tid = threadIdx.x;
    float s = 0.f;
    for (int i = tid; i < 1024; i += 256) { float v = hp[i]; row[i] = v; s += v; }
    for (int o = 16; o; o >>= 1) s += __shfl_xor_sync(~0u, s, o);
    if ((tid & 31) == 0) red[tid >> 5] = s;
    __syncthreads();
    if (tid == 0) { float t = 0; for (int i = 0; i < 8; i++) t += red[i]; meanv = t * (1.f / 1024.f); }
    __syncthreads();
    float m = meanv;
    float ss = 0.f;
    for (int i = tid; i < 1024; i += 256) { float d = row[i] - m; ss += d * d; }
    for (int o = 16; o; o >>= 1) ss += __shfl_xor_sync(~0u, ss, o);
    if ((tid & 31) == 0) red[tid >> 5] = ss;
    __syncthreads();
    if (tid == 0) { float t = 0; for (int i = 0; i < 8; i++) t += red[i]; rstdv = rsqrtf(t * (1.f / 1024.f) + 1e-5f); }
    __syncthreads();
    float rs = rstdv;
    for (int i = tid; i < 1024; i += 256) hp[i] = (row[i] - m) * rs * g[i] + b[i];
}

// ---------------- fused RMSNorm + RoPE (register-level, per warp row) ----------------
__device__ __forceinline__ void rmsrope_w(float& v0, float& v1,
                                          const float* __restrict__ w, int lane, int t)
{
    float ss = v0 * v0 + v1 * v1;
    for (int o = 16; o; o >>= 1) ss += __shfl_xor_sync(~0u, ss, o);
    float rs = rsqrtf(ss * (1.f / 64.f) + 1e-6f);
    v0 = v0 * rs * w[lane];
    v1 = v1 * rs * w[lane + 32];
    float other = __shfl_xor_sync(~0u, v0, 1);
    if (lane < 8) {
        float inv = exp2f(-2.f * (float)(lane >> 1));
        float ang = (float)t * inv;
        float c, s;
        sincosf(ang, &s, &c);
        float rot = (lane & 1) ? other : -other;
        v0 = v0 * c + rot * s;
    }
}

// ---------------- rope+rms on kv k-half (24 rows x 16 heads) ----------------
__global__ void kv_rope(const float* __restrict__ knw)
{
    int t = blockIdx.x;
    int warp = threadIdx.x >> 5, lane = threadIdx.x & 31;  // warp = head
    float* base = g_kvpad + t * 2048 + warp * 64;
    float v0 = base[lane], v1 = base[lane + 32];
    rmsrope_w(v0, v1, knw, lane, t);
    base[lane] = v0; base[lane + 32] = v1;
}

// ---------------- attn1: smem-tiled per (s, h), fused q/k rms+rope ----------------
__global__ void __launch_bounds__(256) attn1(const float* __restrict__ qkv,
                                             float* __restrict__ o,
                                             const float* __restrict__ qn,
                                             const float* __restrict__ kn)
{
    __shared__ float ks[24][64];
    __shared__ float vs[24][64];
    int s = blockIdx.x, h = blockIdx.y;
    int warp = threadIdx.x >> 5, lane = threadIdx.x & 31;

#pragma unroll
    for (int j = 0; j < 3; j++) {
        int t = warp * 3 + j;
        const float* base = qkv + (size_t)(t * 1024 + s) * 3072 + h * 64;
        float k0 = base[1024 + lane], k1 = base[1024 + lane + 32];
        rmsrope_w(k0, k1, kn, lane, t);
        ks[t][lane] = k0; ks[t][lane + 32] = k1;
        vs[t][lane] = base[2048 + lane];
        vs[t][lane + 32] = base[2048 + lane + 32];
    }
    __syncthreads();

#pragma unroll
    for (int j = 0; j < 3; j++) {
        int t = warp * 3 + j;
        const float* qp = qkv + (size_t)(t * 1024 + s) * 3072 + h * 64;
        float q0 = qp[lane], q1 = qp[lane + 32];
        rmsrope_w(q0, q1, qn, lane, t);
        int u0 = max(0, t - 5);
        int nu = t - u0 + 1;
        float sc[6];
        float mx = -1e30f;
#pragma unroll
        for (int i = 0; i < 6; i++) {
            if (i < nu) {
                int uu = u0 + i;
                float d = q0 * ks[uu][lane] + q1 * ks[uu][lane + 32];
                for (int off = 16; off; off >>= 1) d += __shfl_xor_sync(~0u, d, off);
                sc[i] = d * 0.125f;
                mx = fmaxf(mx, sc[i]);
            }
        }
        float denom = 0.f, a0 = 0.f, a1 = 0.f;
#pragma unroll
        for (int i = 0; i < 6; i++) {
            if (i < nu) {
                float p = __expf(sc[i] - mx);
                denom += p;
                int uu = u0 + i;
                a0 += p * vs[uu][lane]; a1 += p * vs[uu][lane + 32];
            }
        }
        float inv = 1.f / denom;
        float* op = o + (size_t)(t * 1024 + s) * 1024 + h * 64;
        op[lane] = a0 * inv; op[lane + 32] = a1 * inv;
    }
}

// ---------------- attn2: keyboard cross-attn, fused q rms+rope ----------------
__global__ void __launch_bounds__(256) attn2(const float* __restrict__ q,
                                             const float* __restrict__ kv,
                                             float* __restrict__ o,
                                             const float* __restrict__ qn)
{
    int item = blockIdx.x * 8 + (threadIdx.x >> 5);
    int lane = threadIdx.x & 31;
    int h = item & 15;
    int r = item >> 4;
    int t = r >> 10;
    int u0 = max(0, t - 5);
    int nu = t - u0 + 1;

    const float* qp = q + (size_t)r * 1024 + h * 64;
    float q0 = qp[lane], q1 = qp[lane + 32];
    rmsrope_w(q0, q1, qn, lane, t);

    float sc[6];
    float mx = -1e30f;
#pragma unroll
    for (int i = 0; i < 6; i++) {
        if (i < nu) {
            int uu = u0 + i;
            const float* kp = kv + (size_t)uu * 2048 + h * 64;
            float d = q0 * kp[lane] + q1 * kp[lane + 32];
            for (int off = 16; off; off >>= 1) d += __shfl_xor_sync(~0u, d, off);
            sc[i] = d * 0.125f;
            mx = fmaxf(mx, sc[i]);
        }
    }
    float denom = 0.f, a0 = 0.f, a1 = 0.f;
#pragma unroll
    for (int i = 0; i < 6; i++) {
        if (i < nu) {
            float p = __expf(sc[i] - mx);
            denom += p;
            int uu = u0 + i;
            const float* vp = kv + (size_t)uu * 2048 + 1024 + h * 64;
            a0 += p * vp[lane]; a1 += p * vp[lane + 32];
        }
    }
    float inv = 1.f / denom;
    float* op = o + (size_t)r * 1024 + h * 64;
    op[lane] = a0 * inv; op[lane + 32] = a1 * inv;
}

// ---------------- conditioning: keyboard MLP (+ mouse gather in block 0) ----------------
__global__ void kb_mlp(const float* __restrict__ kb,
                       const float* __restrict__ w1, const float* __restrict__ b1,
                       const float* __restrict__ w2, const float* __restrict__ b2,
                       const float* __restrict__ mouse)
{
    int n = blockIdx.x;
    int c = threadIdx.x;  // 128
    if (n == 0) {
        for (int i = c; i < TT * 24; i += 128) {
            int t = i / 24, j2 = i % 24;
            g_gm[i] = mouse[(4 * t + (j2 >> 1)) * 2 + (j2 & 1)];
        }
    }
    __shared__ float hid[128];
    float a = b1[c];
#pragma unroll
    for (int i = 0; i < 6; i++) a += kb[n * 6 + i] * w1[i * 128 + c];
    hid[c] = a / (1.f + __expf(-a));
    __syncthreads();
    float ov = b2[c];
    for (int i = 0; i < 128; i++) ov += hid[i] * w2[i * 128 + c];
    g_kc[n * 128 + c] = ov;
}

// ---------------- host ----------------
extern "C" void kernel_launch(void* const* d_in, const int* in_sizes, int n_in,
                              void* d_out, int out_size)
{
    int wb = (in_sizes[3] == 1) ? 6 : 3;
    const float* x       = (const float*)d_in[0];
    const float* mouse   = (const float*)d_in[1];
    const float* kb      = (const float*)d_in[2];
    const float* kb_w1   = (const float*)d_in[wb + 0];
    const float* kb_b1   = (const float*)d_in[wb + 1];
    const float* kb_w2   = (const float*)d_in[wb + 2];
    const float* kb_b2   = (const float*)d_in[wb + 3];
    const float* mm_w1   = (const float*)d_in[wb + 4];
    const float* mm_b1   = (const float*)d_in[wb + 5];
    const float* mm_w2   = (const float*)d_in[wb + 6];
    const float* mm_b2   = (const float*)d_in[wb + 7];
    const float* ln_g    = (const float*)d_in[wb + 8];
    const float* ln_b    = (const float*)d_in[wb + 9];
    const float* qkv_w   = (const float*)d_in[wb + 10];
    const float* qn_img  = (const float*)d_in[wb + 11];
    const float* kn_img  = (const float*)d_in[wb + 12];
    const float* qn_key  = (const float*)d_in[wb + 13];
    const float* kn_key  = (const float*)d_in[wb + 14];
    const float* proj_mouse_w = (const float*)d_in[wb + 15];
    const float* wq_key  = (const float*)d_in[wb + 16];
    const float* wkv_key = (const float*)d_in[wb + 17];
    const float* proj_key_w   = (const float*)d_in[wb + 18];

    float *p_kvpad, *p_h1, *p_h2, *p_qkv, *p_o, *p_hidden, *p_qh, *p_mext, *p_gk24;
    float *w1t, *w2t, *w3t, *w4t, *w5t, *w6t, *w7t;
    cudaGetSymbolAddress((void**)&p_kvpad, g_kvpad);
    cudaGetSymbolAddress((void**)&p_gk24, g_gk24);
    cudaGetSymbolAddress((void**)&p_h1, g_h1);
    cudaGetSymbolAddress((void**)&p_h2, g_h2);
    cudaGetSymbolAddress((void**)&p_qkv, g_qkv);
    cudaGetSymbolAddress((void**)&p_o, g_o);
    cudaGetSymbolAddress((void**)&p_hidden, g_hidden);
    cudaGetSymbolAddress((void**)&p_qh, g_qh);
    cudaGetSymbolAddress((void**)&p_mext, g_mext);
    cudaGetSymbolAddress((void**)&w1t, g_wt1);
    cudaGetSymbolAddress((void**)&w2t, g_wt2);
    cudaGetSymbolAddress((void**)&w3t, g_wt3);
    cudaGetSymbolAddress((void**)&w4t, g_wt4);
    cudaGetSymbolAddress((void**)&w5t, g_wt5);
    cudaGetSymbolAddress((void**)&w6t, g_wt6);
    cudaGetSymbolAddress((void**)&w7t, g_wt7);

    cudaFuncSetAttribute(tgemm, cudaFuncAttributeMaxDynamicSharedMemorySize, GEMM_SMEM);

    // one fused transpose launch for all seven weights
    TPack tp;
    tp.src[0] = mm_w1;        tp.dst[0] = w1t; tp.R[0] = 1560; tp.C[0] = 1024;
    tp.src[1] = mm_w2;        tp.dst[1] = w2t; tp.R[1] = 1024; tp.C[1] = 1024;
    tp.src[2] = qkv_w;        tp.dst[2] = w3t; tp.R[2] = 1024; tp.C[2] = 3072;
    tp.src[3] = proj_mouse_w; tp.dst[3] = w4t; tp.R[3] = 1024; tp.C[3] = 1536;
    tp.src[4] = wq_key;       tp.dst[4] = w5t; tp.R[4] = 1536; tp.C[4] = 1024;
    tp.src[5] = proj_key_w;   tp.dst[5] = w6t; tp.R[5] = 1024; tp.C[5] = 1536;
    tp.src[6] = wkv_key;      tp.dst[6] = w7t; tp.R[6] = 1536; tp.C[6] = 2048;
    transpose_all<<<dim3(96, 49, 7), dim3(32, 8)>>>(tp);

    // conditioning path
    kb_mlp<<<NF, 128>>>(kb, kb_w1, kb_b1, kb_w2, kb_b2, mouse);
    mext_kernel<<<TT, 256>>>(w1t);
    gk_build<<<128, 256>>>();
    // kv = gk24 @ wkv  (M=128 padded, N=2048, K=1536), then rope k-half
    tgemm<<<dim3(2048 / 128, 1), 256, GEMM_SMEM>>>(p_gk24, 1536, w7t, 1536, p_kvpad,
                                                   nullptr, nullptr, nullptr, 2048, 1536, 0);
    kv_rope<<<TT, 512>>>(kn_key);

    const int MB = LTOK / 128;  // 192

    // GEMM1: x @ mm_w1[:1536] + b1 + mext[frame], gelu  (K=1536; mouse tail via extra)
    tgemm<<<dim3(HID / 128, MB), 256, GEMM_SMEM>>>(x, CDIM, w1t, 1560, p_h1,
                                                   mm_b1, nullptr, p_mext, HID, 1536, 1);
    // GEMM2: h1 @ mm_w2 + b2
    tgemm<<<dim3(HID / 128, MB), 256, GEMM_SMEM>>>(p_h1, HID, w2t, HID, p_h2,
                                                   mm_b2, nullptr, nullptr, HID, HID, 0);
    ln_kernel<<<LTOK, 256>>>(p_h2, ln_g, ln_b);

    // GEMM3: qkv
    tgemm<<<dim3(3 * HID / 128, MB), 256, GEMM_SMEM>>>(p_h2, HID, w3t, HID, p_qkv,
                                                       nullptr, nullptr, nullptr, 3 * HID, HID, 0);
    attn1<<<dim3(SSP, NHEAD), 256>>>(p_qkv, p_o, qn_img, kn_img);

    // GEMM4: hidden = x + o @ proj_mouse_w
    tgemm<<<dim3(CDIM / 128, MB), 256, GEMM_SMEM>>>(p_o, HID, w4t, HID, p_hidden,
                                                    nullptr, x, nullptr, CDIM, HID, 2);
    // GEMM5: qh = hidden @ wq_key
    tgemm<<<dim3(HID / 128, MB), 256, GEMM_SMEM>>>(p_hidden, CDIM, w5t, CDIM, p_qh,
                                                   nullptr, nullptr, nullptr, HID, CDIM, 0);
    attn2<<<(LTOK * NHEAD) / 8, 256>>>(p_qh, p_kvpad, p_o, qn_key);

    // GEMM6: out = hidden + o2 @ proj_key_w
    tgemm<<<dim3(CDIM / 128, MB), 256, GEMM_SMEM>>>(p_o, HID, w6t, HID, (float*)d_out,
                                                    nullptr, p_hidden, nullptr, CDIM, HID, 2);
}